// round 10
// baseline (speedup 1.0000x reference)
#include <cuda_runtime.h>
#include <cuda_bf16.h>

#define BB 16
#define CC 512
#define NN 1600
#define NP 1664
#define HC 64
#define L2E8 0.1803368801111204f

typedef unsigned int u32; typedef unsigned short u16;

extern __shared__ __align__(16) unsigned char smdyn[];

// global scratch: bf16 hi/lo plane arrays
__device__ u16 g_Qh[BB*NP*HC], g_Ql[BB*NP*HC];   // Q [b][n][h]
__device__ u16 g_Kh[BB*NP*HC], g_Kl[BB*NP*HC];   // K [b][m][h]
__device__ u16 g_Vh[BB*HC*NP], g_Vl[BB*HC*NP];   // Vt [b][h][m]
__device__ u16 g_Rh[BB*HC*NP], g_Rl[BB*HC*NP];   // resT [b][h][n] flat == res2 [n'][k]
__device__ u16 g_Wh[3*HC*CC],  g_Wl[3*HC*CC];    // wT  [z][h][c] pitch 512
__device__ u16 g_Woh[CC*HC],   g_Wol[CC*HC];     // woT [c][k] pitch 64

__device__ __forceinline__ u32 pack_hl(float x){
    u32 h=__float_as_uint(x)&0xffff0000u; u16 lb;
    asm("cvt.rn.bf16.f32 %0,%1;":"=h"(lb):"f"(x-__uint_as_float(h)));
    return (h>>16)|((u32)lb<<16);
}
__device__ __forceinline__ void split2(float x0,float x1,u32& hi,u32& lo){
    u32 h0=__float_as_uint(x0)&0xffff0000u, h1=__float_as_uint(x1)&0xffff0000u;
    hi=(h0>>16)|h1;
    float l0=x0-__uint_as_float(h0), l1=x1-__uint_as_float(h1);
    asm("cvt.rn.bf16x2.f32 %0,%1,%2;":"=r"(lo):"f"(l1),"f"(l0));
}
__device__ __forceinline__ float ex2f(float x){float r;asm("ex2.approx.ftz.f32 %0,%1;":"=f"(r):"f"(x));return r;}
__device__ __forceinline__ u32 s2u(const void* p){u32 a;asm("{.reg .u64 t; cvta.to.shared.u64 t,%1; cvt.u32.u64 %0,t;}":"=r"(a):"l"(p));return a;}
__device__ __forceinline__ void mmabf(float (&c)[4], u32 a0,u32 a1,u32 a2,u32 a3, u32 b0,u32 b1){
    asm volatile("mma.sync.aligned.m16n8k16.row.col.f32.bf16.bf16.f32 "
        "{%0,%1,%2,%3},{%4,%5,%6,%7},{%8,%9},{%0,%1,%2,%3};"
        : "+f"(c[0]),"+f"(c[1]),"+f"(c[2]),"+f"(c[3])
        : "r"(a0),"r"(a1),"r"(a2),"r"(a3),"r"(b0),"r"(b1));
}
__device__ __forceinline__ void ldsm4(u32 (&r)[4], u32 a){
    asm volatile("ldmatrix.sync.aligned.m8n8.x4.shared.b16 {%0,%1,%2,%3},[%4];"
        :"=r"(r[0]),"=r"(r[1]),"=r"(r[2]),"=r"(r[3]):"r"(a));
}

// ---------------- prep ----------------
__global__ void prep_kernel(const float* __restrict__ wq,const float* __restrict__ wk,
                            const float* __restrict__ wv,const float* __restrict__ wo){
    int i=blockIdx.x*256+threadIdx.x;
    if(i<3*HC*CC){
        int z=i/(HC*CC), r=i%(HC*CC), h=r>>9, c=r&511;
        const float* p=(z==0)?wq:(z==1)?wk:wv;
        u32 v=pack_hl(p[c*HC+h]);
        g_Wh[i]=(u16)v; g_Wl[i]=(u16)(v>>16);
    } else if(i<3*HC*CC+CC*HC){
        int j=i-3*HC*CC, c=j>>6, k=j&63;
        u32 v=pack_hl(wo[k*CC+c]);
        g_Woh[j]=(u16)v; g_Wol[j]=(u16)(v>>16);
    } else {
        int j=i-(3*HC*CC+CC*HC);
        if(j<BB*4096){
            int b=j>>12, t=j&4095;
            size_t o=(size_t)b*HC*NP + HC*NN + t;
            g_Rh[o]=0; g_Rl[o]=0;
        }
    }
}

// ---------------- proj: mma.sync; z=0 -> Q,K from rgb; z=1 -> Vt from hsi ---
// D[h][n] = wT[h][c] @ x[c][n].  A=wT (global), B=x^T [n][c] (smem, dbl-buf).
#define PBUF 36864     // one buffer: Xh(18432B) + Xl(18432B), 128n x 72c u16
__global__ __launch_bounds__(256) void proj_kernel(const float* __restrict__ rgb,
                                                   const float* __restrict__ hsi){
    const int tid=threadIdx.x, lane=tid&31, w=tid>>5;
    const int n0=blockIdx.x*128, b=blockIdx.y, z=blockIdx.z;
    const float* src=(z? hsi:rgb)+(size_t)b*CC*NN;
    const int sel = z? 2 : (w>>2);
    const u16 *Ah_=g_Wh+sel*HC*CC, *Al_=g_Wl+sel*HC*CC;
    const int hf=w&3;
    const int jn0 = z? (w>>2)*4 : 0;
    const int njs = z? 4 : 8;
    const u32 smb=s2u(smdyn);
    const int r4=lane>>2, c2=(lane&3)*2;
    const int mat=lane>>3, mr=((mat>>1)<<3)+(lane&7), hoff=(mat&1)<<3;
    float acc[8][2][4];
    #pragma unroll
    for(int j=0;j<8;j++)
        #pragma unroll
        for(int g=0;g<2;g++){acc[j][g][0]=0;acc[j][g][1]=0;acc[j][g][2]=0;acc[j][g][3]=0;}
    auto stage=[&](int ch,int buf){
        u16* Xh=(u16*)(smdyn+buf*PBUF); u16* Xl=Xh+9216;
        int c0=ch*64;
        #pragma unroll
        for(int t=0;t<32;t++){
            int i=tid+t*256, c=i>>7, n=i&127, gn=n0+n;
            float f=(gn<NN)? src[(size_t)(c0+c)*NN+gn]:0.f;
            u32 v=pack_hl(f);
            Xh[n*72+c]=(u16)v; Xl[n*72+c]=(u16)(v>>16);
        }
    };
    stage(0,0); __syncthreads();
    for(int ch=0;ch<8;ch++){
        const int bsel=ch&1;
        if(ch<7) stage(ch+1,bsel^1);
        const u32 kb=smb+bsel*PBUF;
        const int c0=ch*64;
        #pragma unroll
        for(int ks=0;ks<4;ks++){
            size_t o=(size_t)(hf*16+r4)*CC + c0+ks*16+c2;
            u32 a0h=*(const u32*)(Ah_+o),      a1h=*(const u32*)(Ah_+o+8*CC);
            u32 a2h=*(const u32*)(Ah_+o+8),    a3h=*(const u32*)(Ah_+o+8*CC+8);
            u32 a0l=*(const u32*)(Al_+o),      a1l=*(const u32*)(Al_+o+8*CC);
            u32 a2l=*(const u32*)(Al_+o+8),    a3l=*(const u32*)(Al_+o+8*CC+8);
            for(int j=0;j<njs;j++){
                u32 bh4[4],bl4[4];
                u32 a=kb+(((jn0+j)*16+mr)*72+ks*16+hoff)*2;
                ldsm4(bh4,a); ldsm4(bl4,a+18432);
                mmabf(acc[j][0],a0h,a1h,a2h,a3h,bh4[0],bh4[1]);
                mmabf(acc[j][1],a0h,a1h,a2h,a3h,bh4[2],bh4[3]);
                mmabf(acc[j][0],a0l,a1l,a2l,a3l,bh4[0],bh4[1]);
                mmabf(acc[j][1],a0l,a1l,a2l,a3l,bh4[2],bh4[3]);
                mmabf(acc[j][0],a0h,a1h,a2h,a3h,bl4[0],bl4[1]);
                mmabf(acc[j][1],a0h,a1h,a2h,a3h,bl4[2],bl4[3]);
            }
        }
        __syncthreads();
    }
    // epilogue via smem f32 tile [64h][132n]
    float* Of=(float*)smdyn;
    const int npass=z?1:2;
    for(int ps=0;ps<npass;ps++){
        if(z || (w>>2)==ps){
            #pragma unroll
            for(int j=0;j<8;j++){
                if(j>=njs) break;
                int h=hf*16+r4, n=(jn0+j)*16+c2;
                Of[h*132+n]=acc[j][0][0];     Of[h*132+n+1]=acc[j][0][1];
                Of[(h+8)*132+n]=acc[j][0][2]; Of[(h+8)*132+n+1]=acc[j][0][3];
                Of[h*132+n+8]=acc[j][1][0];   Of[h*132+n+9]=acc[j][1][1];
                Of[(h+8)*132+n+8]=acc[j][1][2]; Of[(h+8)*132+n+9]=acc[j][1][3];
            }
        }
        __syncthreads();
        u16 *oh,*ol;
        if(z){oh=g_Vh;ol=g_Vl;} else {oh=ps?g_Kh:g_Qh; ol=ps?g_Kl:g_Ql;}
        oh+=(size_t)b*NP*HC; ol+=(size_t)b*NP*HC;
        if(z){   // Vt [h][m] pitch NP
            for(int i=tid;i<8192;i+=256){
                int h=i>>7, n=i&127, gn=n0+n;
                if(gn<NN){ u32 v=pack_hl(Of[h*132+n]);
                    oh[(size_t)h*NP+gn]=(u16)v; ol[(size_t)h*NP+gn]=(u16)(v>>16); }
            }
        } else { // Q/K [n][h] pitch HC
            for(int i=tid;i<8192;i+=256){
                int n=i>>6, h=i&63, gn=n0+n;
                if(gn<NN){ u32 v=pack_hl(Of[h*132+n]);
                    oh[(size_t)gn*HC+h]=(u16)v; ol[(size_t)gn*HC+h]=(u16)(v>>16); }
            }
        }
        __syncthreads();
    }
}

// ---------------- attn: FA2-style mma.sync (unchanged from R9) --------------
#define TILEB 9216
#define BUFB  36864
__global__ __launch_bounds__(256) void attn_kernel(){
    unsigned char* sm=smdyn;
    const int tid=threadIdx.x, lane=tid&31, warp=tid>>5;
    const int n0=blockIdx.x*128, b=blockIdx.y;
    const size_t qb=(size_t)b*NP*HC, vb=(size_t)b*HC*NP;
    const u16 *Qhp=g_Qh+qb,*Qlp=g_Ql+qb,*Khp=g_Kh+qb,*Klp=g_Kl+qb;
    const u16 *Vhp=g_Vh+vb,*Vlp=g_Vl+vb;
    const u32 smb=s2u(sm);
    const int q0=n0+warp*16, r4=lane>>2, c2=(lane&3)*2;
    u32 qh[4][4], ql[4][4];
    #pragma unroll
    for(int ks=0;ks<4;ks++){
        size_t o00=(size_t)(q0+r4)*HC+ks*16+c2, o10=o00+8*HC, o01=o00+8, o11=o10+8;
        qh[ks][0]=*(const u32*)(Qhp+o00); qh[ks][1]=*(const u32*)(Qhp+o10);
        qh[ks][2]=*(const u32*)(Qhp+o01); qh[ks][3]=*(const u32*)(Qhp+o11);
        ql[ks][0]=*(const u32*)(Qlp+o00); ql[ks][1]=*(const u32*)(Qlp+o10);
        ql[ks][2]=*(const u32*)(Qlp+o01); ql[ks][3]=*(const u32*)(Qlp+o11);
    }
    const int mat=lane>>3, mr=((mat>>1)<<3)+(lane&7), hoff=(mat&1)<<3;
    float O[8][4];
    #pragma unroll
    for(int j=0;j<8;j++){O[j][0]=0;O[j][1]=0;O[j][2]=0;O[j][3]=0;}
    float rsA=0.f, rsB=0.f;
    auto loadt=[&](int m0, unsigned char* buf){
        u32* kh=(u32*)buf; u32* kl=(u32*)(buf+TILEB);
        u32* vh=(u32*)(buf+2*TILEB); u32* vl=(u32*)(buf+3*TILEB);
        #pragma unroll
        for(int t=0;t<8;t++){
            int i=tid+t*256, r=i>>5, w=i&31;
            kh[r*36+w]=((const u32*)(Khp+(size_t)(m0+r)*HC))[w];
            kl[r*36+w]=((const u32*)(Klp+(size_t)(m0+r)*HC))[w];
            vh[r*36+w]=((const u32*)(Vhp+(size_t)r*NP+m0))[w];
            vl[r*36+w]=((const u32*)(Vlp+(size_t)r*NP+m0))[w];
        }
    };
    loadt(0, sm);
    __syncthreads();
    for(int it=0; it<25; it++){
        const int bsel=it&1;
        if(it<24) loadt((it+1)*64, sm+(bsel^1)*BUFB);
        const u32 kb=smb+bsel*BUFB;
        u32 Ph[4][4], Pl[4][4];
        #pragma unroll
        for(int jj=0;jj<4;jj++){
            float c0[4]={0,0,0,0}, c1[4]={0,0,0,0};
            #pragma unroll
            for(int ks=0;ks<4;ks++){
                u32 kh4[4],kl4[4];
                u32 a=kb+(((jj*16+mr)*72)+ks*16+hoff)*2;
                ldsm4(kh4,a); ldsm4(kl4,a+TILEB);
                mmabf(c0,qh[ks][0],qh[ks][1],qh[ks][2],qh[ks][3],kh4[0],kh4[1]);
                mmabf(c1,qh[ks][0],qh[ks][1],qh[ks][2],qh[ks][3],kh4[2],kh4[3]);
                mmabf(c0,ql[ks][0],ql[ks][1],ql[ks][2],ql[ks][3],kh4[0],kh4[1]);
                mmabf(c1,ql[ks][0],ql[ks][1],ql[ks][2],ql[ks][3],kh4[2],kh4[3]);
                mmabf(c0,qh[ks][0],qh[ks][1],qh[ks][2],qh[ks][3],kl4[0],kl4[1]);
                mmabf(c1,qh[ks][0],qh[ks][1],qh[ks][2],qh[ks][3],kl4[2],kl4[3]);
            }
            #pragma unroll
            for(int e=0;e<4;e++){ c0[e]=ex2f(c0[e]*L2E8); c1[e]=ex2f(c1[e]*L2E8); }
            rsA += (c0[0]+c0[1])+(c1[0]+c1[1]);
            rsB += (c0[2]+c0[3])+(c1[2]+c1[3]);
            split2(c0[0],c0[1],Ph[jj][0],Pl[jj][0]);
            split2(c0[2],c0[3],Ph[jj][1],Pl[jj][1]);
            split2(c1[0],c1[1],Ph[jj][2],Pl[jj][2]);
            split2(c1[2],c1[3],Ph[jj][3],Pl[jj][3]);
        }
        #pragma unroll
        for(int jj=0;jj<4;jj++){
            #pragma unroll
            for(int hh=0;hh<4;hh++){
                u32 vh4[4],vl4[4];
                u32 a=kb+2*TILEB+(((hh*16+mr)*72)+jj*16+hoff)*2;
                ldsm4(vh4,a); ldsm4(vl4,a+TILEB);
                mmabf(O[hh*2],  Ph[jj][0],Ph[jj][1],Ph[jj][2],Ph[jj][3],vh4[0],vh4[1]);
                mmabf(O[hh*2+1],Ph[jj][0],Ph[jj][1],Ph[jj][2],Ph[jj][3],vh4[2],vh4[3]);
                mmabf(O[hh*2],  Pl[jj][0],Pl[jj][1],Pl[jj][2],Pl[jj][3],vh4[0],vh4[1]);
                mmabf(O[hh*2+1],Pl[jj][0],Pl[jj][1],Pl[jj][2],Pl[jj][3],vh4[2],vh4[3]);
                mmabf(O[hh*2],  Ph[jj][0],Ph[jj][1],Ph[jj][2],Ph[jj][3],vl4[0],vl4[1]);
                mmabf(O[hh*2+1],Ph[jj][0],Ph[jj][1],Ph[jj][2],Ph[jj][3],vl4[2],vl4[3]);
            }
        }
        __syncthreads();
    }
    rsA += __shfl_xor_sync(0xffffffffu,rsA,1); rsA += __shfl_xor_sync(0xffffffffu,rsA,2);
    rsB += __shfl_xor_sync(0xffffffffu,rsB,1); rsB += __shfl_xor_sync(0xffffffffu,rsB,2);
    const float invA=1.f/rsA, invB=1.f/rsB;
    float* Of=(float*)sm;
    #pragma unroll
    for(int j=0;j<8;j++){
        int h=j*8+c2;
        Of[(warp*16+r4)*68+h  ]=O[j][0]*invA;
        Of[(warp*16+r4)*68+h+1]=O[j][1]*invA;
        Of[(warp*16+r4+8)*68+h  ]=O[j][2]*invB;
        Of[(warp*16+r4+8)*68+h+1]=O[j][3]*invB;
    }
    __syncthreads();
    u16 *Rh=g_Rh+(size_t)b*HC*NP, *Rl=g_Rl+(size_t)b*HC*NP;
    for(int i=tid;i<8192;i+=256){
        int h=i>>7, n=i&127, gn=n0+n;
        if(gn<NN){
            u32 v=pack_hl(Of[n*68+h]);
            Rh[(size_t)h*NN+gn]=(u16)v; Rl[(size_t)h*NN+gn]=(u16)(v>>16);
        }
    }
}

// ---------------- out: mma.sync; A=woT (global), B=res2 tile (smem) ---------
__global__ __launch_bounds__(256) void out_kernel(float* __restrict__ out){
    const int tid=threadIdx.x, lane=tid&31, w=tid>>5;
    const int n0=blockIdx.x*128, c0=blockIdx.y*128, b=blockIdx.z;
    const u32* sRh=(const u32*)(g_Rh+(size_t)b*HC*NP);
    const u32* sRl=(const u32*)(g_Rl+(size_t)b*HC*NP);
    u32* kh=(u32*)smdyn; u32* kl=(u32*)(smdyn+18432);
    #pragma unroll
    for(int t=0;t<16;t++){
        int i=tid+t*256, r=i>>5, ww=i&31;
        kh[r*36+ww]=sRh[(size_t)(n0+r)*32+ww];
        kl[r*36+ww]=sRl[(size_t)(n0+r)*32+ww];
    }
    __syncthreads();
    const u32 smb=s2u(smdyn);
    const int r4=lane>>2, c2=(lane&3)*2;
    const int mat=lane>>3, mr=((mat>>1)<<3)+(lane&7), hoff=(mat&1)<<3;
    float acc[8][2][4];
    #pragma unroll
    for(int j=0;j<8;j++)
        #pragma unroll
        for(int g=0;g<2;g++){acc[j][g][0]=0;acc[j][g][1]=0;acc[j][g][2]=0;acc[j][g][3]=0;}
    #pragma unroll
    for(int ks=0;ks<4;ks++){
        size_t o=(size_t)(c0+w*16+r4)*HC + ks*16+c2;
        u32 a0h=*(const u32*)(g_Woh+o),   a1h=*(const u32*)(g_Woh+o+8*HC);
        u32 a2h=*(const u32*)(g_Woh+o+8), a3h=*(const u32*)(g_Woh+o+8*HC+8);
        u32 a0l=*(const u32*)(g_Wol+o),   a1l=*(const u32*)(g_Wol+o+8*HC);
        u32 a2l=*(const u32*)(g_Wol+o+8), a3l=*(const u32*)(g_Wol+o+8*HC+8);
        #pragma unroll
        for(int j=0;j<8;j++){
            u32 bh4[4],bl4[4];
            u32 a=smb+((j*16+mr)*72+ks*16+hoff)*2;
            ldsm4(bh4,a); ldsm4(bl4,a+18432);
            mmabf(acc[j][0],a0h,a1h,a2h,a3h,bh4[0],bh4[1]);
            mmabf(acc[j][1],a0h,a1h,a2h,a3h,bh4[2],bh4[3]);
            mmabf(acc[j][0],a0l,a1l,a2l,a3l,bh4[0],bh4[1]);
            mmabf(acc[j][1],a0l,a1l,a2l,a3l,bh4[2],bh4[3]);
            mmabf(acc[j][0],a0h,a1h,a2h,a3h,bl4[0],bl4[1]);
            mmabf(acc[j][1],a0h,a1h,a2h,a3h,bl4[2],bl4[3]);
        }
    }
    float* ob=out+(size_t)b*CC*NN;
    const int cc=c0+w*16+r4;
    #pragma unroll
    for(int j=0;j<8;j++){
        int nn=n0+j*16+c2;
        if(nn<NN){
            *(float2*)&ob[(size_t)cc*NN+nn]    =make_float2(acc[j][0][0],acc[j][0][1]);
            *(float2*)&ob[(size_t)(cc+8)*NN+nn]=make_float2(acc[j][0][2],acc[j][0][3]);
        }
        int n2=nn+8;
        if(n2<NN){
            *(float2*)&ob[(size_t)cc*NN+n2]    =make_float2(acc[j][1][0],acc[j][1][1]);
            *(float2*)&ob[(size_t)(cc+8)*NN+n2]=make_float2(acc[j][1][2],acc[j][1][3]);
        }
    }
}

extern "C" void kernel_launch(void* const* d_in, const int* in_sizes, int n_in,
                              void* d_out, int out_size){
    const float* rgb=(const float*)d_in[0];
    const float* hsi=(const float*)d_in[1];
    const float* wq =(const float*)d_in[2];
    const float* wk =(const float*)d_in[3];
    const float* wv =(const float*)d_in[4];
    const float* wo =(const float*)d_in[5];
    float* out=(float*)d_out;

    cudaFuncSetAttribute(proj_kernel, cudaFuncAttributeMaxDynamicSharedMemorySize, 2*PBUF);
    cudaFuncSetAttribute(attn_kernel, cudaFuncAttributeMaxDynamicSharedMemorySize, 2*BUFB);
    prep_kernel<<<768,256>>>(wq,wk,wv,wo);
    proj_kernel<<<dim3(13,BB,2),256,2*PBUF>>>(rgb,hsi);
    attn_kernel<<<dim3(13,BB),256,2*BUFB>>>();
    out_kernel<<<dim3(13,4,BB),256,36864>>>(out);
}

// round 11
// speedup vs baseline: 1.5393x; 1.5393x over previous
#include <cuda_runtime.h>
#include <cuda_bf16.h>

#define BB 16
#define CC 512
#define NN 1600
#define NP 1664
#define HC 64
#define L2E8 0.1803368801111204f

typedef unsigned int u32; typedef unsigned short u16;

extern __shared__ __align__(16) unsigned char smdyn[];

// global scratch: bf16 hi/lo plane arrays
__device__ u16 g_Qh[BB*NP*HC], g_Ql[BB*NP*HC];   // Q [b][n][h]
__device__ u16 g_Kh[BB*NP*HC], g_Kl[BB*NP*HC];   // K [b][m][h]
__device__ u16 g_Vh[BB*HC*NP], g_Vl[BB*HC*NP];   // Vt [b][h][m]
__device__ u16 g_Rh[BB*HC*NP], g_Rl[BB*HC*NP];   // resT [b][h][n] flat == res2 [n'][k]
__device__ u16 g_Wh[3*HC*CC],  g_Wl[3*HC*CC];    // wT  [z][h][c] pitch 512
__device__ u16 g_Woh[CC*HC],   g_Wol[CC*HC];     // woT [c][k] pitch 64

__device__ __forceinline__ u32 pack_hl(float x){
    u32 h=__float_as_uint(x)&0xffff0000u; u16 lb;
    asm("cvt.rn.bf16.f32 %0,%1;":"=h"(lb):"f"(x-__uint_as_float(h)));
    return (h>>16)|((u32)lb<<16);
}
__device__ __forceinline__ void split2(float x0,float x1,u32& hi,u32& lo){
    u32 h0=__float_as_uint(x0)&0xffff0000u, h1=__float_as_uint(x1)&0xffff0000u;
    hi=(h0>>16)|h1;
    float l0=x0-__uint_as_float(h0), l1=x1-__uint_as_float(h1);
    asm("cvt.rn.bf16x2.f32 %0,%1,%2;":"=r"(lo):"f"(l1),"f"(l0));
}
__device__ __forceinline__ float ex2f(float x){float r;asm("ex2.approx.ftz.f32 %0,%1;":"=f"(r):"f"(x));return r;}
__device__ __forceinline__ u32 s2u(const void* p){u32 a;asm("{.reg .u64 t; cvta.to.shared.u64 t,%1; cvt.u32.u64 %0,t;}":"=r"(a):"l"(p));return a;}
__device__ __forceinline__ void mmabf(float (&c)[4], u32 a0,u32 a1,u32 a2,u32 a3, u32 b0,u32 b1){
    asm volatile("mma.sync.aligned.m16n8k16.row.col.f32.bf16.bf16.f32 "
        "{%0,%1,%2,%3},{%4,%5,%6,%7},{%8,%9},{%0,%1,%2,%3};"
        : "+f"(c[0]),"+f"(c[1]),"+f"(c[2]),"+f"(c[3])
        : "r"(a0),"r"(a1),"r"(a2),"r"(a3),"r"(b0),"r"(b1));
}
__device__ __forceinline__ void ldsm4(u32 (&r)[4], u32 a){
    asm volatile("ldmatrix.sync.aligned.m8n8.x4.shared.b16 {%0,%1,%2,%3},[%4];"
        :"=r"(r[0]),"=r"(r[1]),"=r"(r[2]),"=r"(r[3]):"r"(a));
}

// ---------------- prep ----------------
__global__ void prep_kernel(const float* __restrict__ wq,const float* __restrict__ wk,
                            const float* __restrict__ wv,const float* __restrict__ wo){
    int i=blockIdx.x*256+threadIdx.x;
    if(i<3*HC*CC){
        int z=i/(HC*CC), r=i%(HC*CC), h=r>>9, c=r&511;
        const float* p=(z==0)?wq:(z==1)?wk:wv;
        u32 v=pack_hl(p[c*HC+h]);
        g_Wh[i]=(u16)v; g_Wl[i]=(u16)(v>>16);
    } else if(i<3*HC*CC+CC*HC){
        int j=i-3*HC*CC, c=j>>6, k=j&63;
        u32 v=pack_hl(wo[k*CC+c]);
        g_Woh[j]=(u16)v; g_Wol[j]=(u16)(v>>16);
    } else {
        int j=i-(3*HC*CC+CC*HC);
        if(j<BB*4096){
            int b=j>>12, t=j&4095;
            size_t o=(size_t)b*HC*NP + HC*NN + t;
            g_Rh[o]=0; g_Rl[o]=0;
        }
    }
}

// ---------------- proj: mma.sync, templated on Z (compile-time tiles) -------
// D[h][n] = wT[h][c] @ x[c][n].  A=wT (global), B=x^T [n][c] (smem, dbl-buf).
#define PBUF 36864     // one buffer: Xh(18432B) + Xl(18432B), 128n x 72c u16
template<int Z>
__global__ __launch_bounds__(256) void proj_kernel(const float* __restrict__ src_all){
    const int tid=threadIdx.x, lane=tid&31, w=tid>>5;
    const int n0=blockIdx.x*128, b=blockIdx.y;
    const float* src=src_all+(size_t)b*CC*NN;
    constexpr int NJS = Z? 4 : 8;
    const int sel = Z? 2 : (w>>2);
    const u16 *Ah_=g_Wh+sel*HC*CC, *Al_=g_Wl+sel*HC*CC;
    const int hf=w&3;
    const int jn0 = Z? (w>>2)*4 : 0;
    const u32 smb=s2u(smdyn);
    const int r4=lane>>2, c2=(lane&3)*2;
    const int mat=lane>>3, mr=((mat>>1)<<3)+(lane&7), hoff=(mat&1)<<3;
    float acc[NJS][2][4];
    #pragma unroll
    for(int j=0;j<NJS;j++)
        #pragma unroll
        for(int g=0;g<2;g++){acc[j][g][0]=0;acc[j][g][1]=0;acc[j][g][2]=0;acc[j][g][3]=0;}
    auto stage=[&](int ch,int buf){
        u16* Xh=(u16*)(smdyn+buf*PBUF); u16* Xl=Xh+9216;
        int c0=ch*64;
        #pragma unroll
        for(int t=0;t<32;t++){
            int i=tid+t*256, c=i>>7, n=i&127, gn=n0+n;
            float f=(gn<NN)? src[(size_t)(c0+c)*NN+gn]:0.f;
            u32 v=pack_hl(f);
            Xh[n*72+c]=(u16)v; Xl[n*72+c]=(u16)(v>>16);
        }
    };
    stage(0,0); __syncthreads();
    for(int ch=0;ch<8;ch++){
        const int bsel=ch&1;
        if(ch<7) stage(ch+1,bsel^1);
        const u32 kb=smb+bsel*PBUF;
        const int c0=ch*64;
        #pragma unroll
        for(int ks=0;ks<4;ks++){
            size_t o=(size_t)(hf*16+r4)*CC + c0+ks*16+c2;
            u32 a0h=*(const u32*)(Ah_+o),      a1h=*(const u32*)(Ah_+o+8*CC);
            u32 a2h=*(const u32*)(Ah_+o+8),    a3h=*(const u32*)(Ah_+o+8*CC+8);
            u32 a0l=*(const u32*)(Al_+o),      a1l=*(const u32*)(Al_+o+8*CC);
            u32 a2l=*(const u32*)(Al_+o+8),    a3l=*(const u32*)(Al_+o+8*CC+8);
            #pragma unroll
            for(int j=0;j<NJS;j++){
                u32 bh4[4],bl4[4];
                u32 a=kb+(((jn0+j)*16+mr)*72+ks*16+hoff)*2;
                ldsm4(bh4,a); ldsm4(bl4,a+18432);
                mmabf(acc[j][0],a0h,a1h,a2h,a3h,bh4[0],bh4[1]);
                mmabf(acc[j][1],a0h,a1h,a2h,a3h,bh4[2],bh4[3]);
                mmabf(acc[j][0],a0l,a1l,a2l,a3l,bh4[0],bh4[1]);
                mmabf(acc[j][1],a0l,a1l,a2l,a3l,bh4[2],bh4[3]);
                mmabf(acc[j][0],a0h,a1h,a2h,a3h,bl4[0],bl4[1]);
                mmabf(acc[j][1],a0h,a1h,a2h,a3h,bl4[2],bl4[3]);
            }
        }
        __syncthreads();
    }
    // epilogue via smem f32 tile [64h][132n]
    float* Of=(float*)smdyn;
    constexpr int NPASS=Z?1:2;
    for(int ps=0;ps<NPASS;ps++){
        if(Z || (w>>2)==ps){
            #pragma unroll
            for(int j=0;j<NJS;j++){
                int h=hf*16+r4, n=(jn0+j)*16+c2;
                Of[h*132+n]=acc[j][0][0];     Of[h*132+n+1]=acc[j][0][1];
                Of[(h+8)*132+n]=acc[j][0][2]; Of[(h+8)*132+n+1]=acc[j][0][3];
                Of[h*132+n+8]=acc[j][1][0];   Of[h*132+n+9]=acc[j][1][1];
                Of[(h+8)*132+n+8]=acc[j][1][2]; Of[(h+8)*132+n+9]=acc[j][1][3];
            }
        }
        __syncthreads();
        u16 *oh,*ol;
        if(Z){oh=g_Vh;ol=g_Vl;} else {oh=ps?g_Kh:g_Qh; ol=ps?g_Kl:g_Ql;}
        oh+=(size_t)b*NP*HC; ol+=(size_t)b*NP*HC;
        if(Z){   // Vt [h][m] pitch NP
            for(int i=tid;i<8192;i+=256){
                int h=i>>7, n=i&127, gn=n0+n;
                if(gn<NN){ u32 v=pack_hl(Of[h*132+n]);
                    oh[(size_t)h*NP+gn]=(u16)v; ol[(size_t)h*NP+gn]=(u16)(v>>16); }
            }
        } else { // Q/K [n][h] pitch HC
            for(int i=tid;i<8192;i+=256){
                int n=i>>6, h=i&63, gn=n0+n;
                if(gn<NN){ u32 v=pack_hl(Of[h*132+n]);
                    oh[(size_t)gn*HC+h]=(u16)v; ol[(size_t)gn*HC+h]=(u16)(v>>16); }
            }
        }
        __syncthreads();
    }
}

// ---------------- attn: FA2-style mma.sync (unchanged) ----------------------
#define TILEB 9216
#define BUFB  36864
__global__ __launch_bounds__(256) void attn_kernel(){
    unsigned char* sm=smdyn;
    const int tid=threadIdx.x, lane=tid&31, warp=tid>>5;
    const int n0=blockIdx.x*128, b=blockIdx.y;
    const size_t qb=(size_t)b*NP*HC, vb=(size_t)b*HC*NP;
    const u16 *Qhp=g_Qh+qb,*Qlp=g_Ql+qb,*Khp=g_Kh+qb,*Klp=g_Kl+qb;
    const u16 *Vhp=g_Vh+vb,*Vlp=g_Vl+vb;
    const u32 smb=s2u(sm);
    const int q0=n0+warp*16, r4=lane>>2, c2=(lane&3)*2;
    u32 qh[4][4], ql[4][4];
    #pragma unroll
    for(int ks=0;ks<4;ks++){
        size_t o00=(size_t)(q0+r4)*HC+ks*16+c2, o10=o00+8*HC, o01=o00+8, o11=o10+8;
        qh[ks][0]=*(const u32*)(Qhp+o00); qh[ks][1]=*(const u32*)(Qhp+o10);
        qh[ks][2]=*(const u32*)(Qhp+o01); qh[ks][3]=*(const u32*)(Qhp+o11);
        ql[ks][0]=*(const u32*)(Qlp+o00); ql[ks][1]=*(const u32*)(Qlp+o10);
        ql[ks][2]=*(const u32*)(Qlp+o01); ql[ks][3]=*(const u32*)(Qlp+o11);
    }
    const int mat=lane>>3, mr=((mat>>1)<<3)+(lane&7), hoff=(mat&1)<<3;
    float O[8][4];
    #pragma unroll
    for(int j=0;j<8;j++){O[j][0]=0;O[j][1]=0;O[j][2]=0;O[j][3]=0;}
    float rsA=0.f, rsB=0.f;
    auto loadt=[&](int m0, unsigned char* buf){
        u32* kh=(u32*)buf; u32* kl=(u32*)(buf+TILEB);
        u32* vh=(u32*)(buf+2*TILEB); u32* vl=(u32*)(buf+3*TILEB);
        #pragma unroll
        for(int t=0;t<8;t++){
            int i=tid+t*256, r=i>>5, w=i&31;
            kh[r*36+w]=((const u32*)(Khp+(size_t)(m0+r)*HC))[w];
            kl[r*36+w]=((const u32*)(Klp+(size_t)(m0+r)*HC))[w];
            vh[r*36+w]=((const u32*)(Vhp+(size_t)r*NP+m0))[w];
            vl[r*36+w]=((const u32*)(Vlp+(size_t)r*NP+m0))[w];
        }
    };
    loadt(0, sm);
    __syncthreads();
    for(int it=0; it<25; it++){
        const int bsel=it&1;
        if(it<24) loadt((it+1)*64, sm+(bsel^1)*BUFB);
        const u32 kb=smb+bsel*BUFB;
        u32 Ph[4][4], Pl[4][4];
        #pragma unroll
        for(int jj=0;jj<4;jj++){
            float c0[4]={0,0,0,0}, c1[4]={0,0,0,0};
            #pragma unroll
            for(int ks=0;ks<4;ks++){
                u32 kh4[4],kl4[4];
                u32 a=kb+(((jj*16+mr)*72)+ks*16+hoff)*2;
                ldsm4(kh4,a); ldsm4(kl4,a+TILEB);
                mmabf(c0,qh[ks][0],qh[ks][1],qh[ks][2],qh[ks][3],kh4[0],kh4[1]);
                mmabf(c1,qh[ks][0],qh[ks][1],qh[ks][2],qh[ks][3],kh4[2],kh4[3]);
                mmabf(c0,ql[ks][0],ql[ks][1],ql[ks][2],ql[ks][3],kh4[0],kh4[1]);
                mmabf(c1,ql[ks][0],ql[ks][1],ql[ks][2],ql[ks][3],kh4[2],kh4[3]);
                mmabf(c0,qh[ks][0],qh[ks][1],qh[ks][2],qh[ks][3],kl4[0],kl4[1]);
                mmabf(c1,qh[ks][0],qh[ks][1],qh[ks][2],qh[ks][3],kl4[2],kl4[3]);
            }
            #pragma unroll
            for(int e=0;e<4;e++){ c0[e]=ex2f(c0[e]*L2E8); c1[e]=ex2f(c1[e]*L2E8); }
            rsA += (c0[0]+c0[1])+(c1[0]+c1[1]);
            rsB += (c0[2]+c0[3])+(c1[2]+c1[3]);
            split2(c0[0],c0[1],Ph[jj][0],Pl[jj][0]);
            split2(c0[2],c0[3],Ph[jj][1],Pl[jj][1]);
            split2(c1[0],c1[1],Ph[jj][2],Pl[jj][2]);
            split2(c1[2],c1[3],Ph[jj][3],Pl[jj][3]);
        }
        #pragma unroll
        for(int jj=0;jj<4;jj++){
            #pragma unroll
            for(int hh=0;hh<4;hh++){
                u32 vh4[4],vl4[4];
                u32 a=kb+2*TILEB+(((hh*16+mr)*72)+jj*16+hoff)*2;
                ldsm4(vh4,a); ldsm4(vl4,a+TILEB);
                mmabf(O[hh*2],  Ph[jj][0],Ph[jj][1],Ph[jj][2],Ph[jj][3],vh4[0],vh4[1]);
                mmabf(O[hh*2+1],Ph[jj][0],Ph[jj][1],Ph[jj][2],Ph[jj][3],vh4[2],vh4[3]);
                mmabf(O[hh*2],  Pl[jj][0],Pl[jj][1],Pl[jj][2],Pl[jj][3],vh4[0],vh4[1]);
                mmabf(O[hh*2+1],Pl[jj][0],Pl[jj][1],Pl[jj][2],Pl[jj][3],vh4[2],vh4[3]);
                mmabf(O[hh*2],  Ph[jj][0],Ph[jj][1],Ph[jj][2],Ph[jj][3],vl4[0],vl4[1]);
                mmabf(O[hh*2+1],Ph[jj][0],Ph[jj][1],Ph[jj][2],Ph[jj][3],vl4[2],vl4[3]);
            }
        }
        __syncthreads();
    }
    rsA += __shfl_xor_sync(0xffffffffu,rsA,1); rsA += __shfl_xor_sync(0xffffffffu,rsA,2);
    rsB += __shfl_xor_sync(0xffffffffu,rsB,1); rsB += __shfl_xor_sync(0xffffffffu,rsB,2);
    const float invA=1.f/rsA, invB=1.f/rsB;
    float* Of=(float*)sm;
    #pragma unroll
    for(int j=0;j<8;j++){
        int h=j*8+c2;
        Of[(warp*16+r4)*68+h  ]=O[j][0]*invA;
        Of[(warp*16+r4)*68+h+1]=O[j][1]*invA;
        Of[(warp*16+r4+8)*68+h  ]=O[j][2]*invB;
        Of[(warp*16+r4+8)*68+h+1]=O[j][3]*invB;
    }
    __syncthreads();
    u16 *Rh=g_Rh+(size_t)b*HC*NP, *Rl=g_Rl+(size_t)b*HC*NP;
    for(int i=tid;i<8192;i+=256){
        int h=i>>7, n=i&127, gn=n0+n;
        if(gn<NN){
            u32 v=pack_hl(Of[n*68+h]);
            Rh[(size_t)h*NN+gn]=(u16)v; Rl[(size_t)h*NN+gn]=(u16)(v>>16);
        }
    }
}

// ---------------- out: mma.sync (unchanged from R10) ------------------------
__global__ __launch_bounds__(256) void out_kernel(float* __restrict__ out){
    const int tid=threadIdx.x, lane=tid&31, w=tid>>5;
    const int n0=blockIdx.x*128, c0=blockIdx.y*128, b=blockIdx.z;
    const u32* sRh=(const u32*)(g_Rh+(size_t)b*HC*NP);
    const u32* sRl=(const u32*)(g_Rl+(size_t)b*HC*NP);
    u32* kh=(u32*)smdyn; u32* kl=(u32*)(smdyn+18432);
    #pragma unroll
    for(int t=0;t<16;t++){
        int i=tid+t*256, r=i>>5, ww=i&31;
        kh[r*36+ww]=sRh[(size_t)(n0+r)*32+ww];
        kl[r*36+ww]=sRl[(size_t)(n0+r)*32+ww];
    }
    __syncthreads();
    const u32 smb=s2u(smdyn);
    const int r4=lane>>2, c2=(lane&3)*2;
    const int mat=lane>>3, mr=((mat>>1)<<3)+(lane&7), hoff=(mat&1)<<3;
    float acc[8][2][4];
    #pragma unroll
    for(int j=0;j<8;j++)
        #pragma unroll
        for(int g=0;g<2;g++){acc[j][g][0]=0;acc[j][g][1]=0;acc[j][g][2]=0;acc[j][g][3]=0;}
    #pragma unroll
    for(int ks=0;ks<4;ks++){
        size_t o=(size_t)(c0+w*16+r4)*HC + ks*16+c2;
        u32 a0h=*(const u32*)(g_Woh+o),   a1h=*(const u32*)(g_Woh+o+8*HC);
        u32 a2h=*(const u32*)(g_Woh+o+8), a3h=*(const u32*)(g_Woh+o+8*HC+8);
        u32 a0l=*(const u32*)(g_Wol+o),   a1l=*(const u32*)(g_Wol+o+8*HC);
        u32 a2l=*(const u32*)(g_Wol+o+8), a3l=*(const u32*)(g_Wol+o+8*HC+8);
        #pragma unroll
        for(int j=0;j<8;j++){
            u32 bh4[4],bl4[4];
            u32 a=smb+((j*16+mr)*72+ks*16+hoff)*2;
            ldsm4(bh4,a); ldsm4(bl4,a+18432);
            mmabf(acc[j][0],a0h,a1h,a2h,a3h,bh4[0],bh4[1]);
            mmabf(acc[j][1],a0h,a1h,a2h,a3h,bh4[2],bh4[3]);
            mmabf(acc[j][0],a0l,a1l,a2l,a3l,bh4[0],bh4[1]);
            mmabf(acc[j][1],a0l,a1l,a2l,a3l,bh4[2],bh4[3]);
            mmabf(acc[j][0],a0h,a1h,a2h,a3h,bl4[0],bl4[1]);
            mmabf(acc[j][1],a0h,a1h,a2h,a3h,bl4[2],bl4[3]);
        }
    }
    float* ob=out+(size_t)b*CC*NN;
    const int cc=c0+w*16+r4;
    #pragma unroll
    for(int j=0;j<8;j++){
        int nn=n0+j*16+c2;
        if(nn<NN){
            *(float2*)&ob[(size_t)cc*NN+nn]    =make_float2(acc[j][0][0],acc[j][0][1]);
            *(float2*)&ob[(size_t)(cc+8)*NN+nn]=make_float2(acc[j][0][2],acc[j][0][3]);
        }
        int n2=nn+8;
        if(n2<NN){
            *(float2*)&ob[(size_t)cc*NN+n2]    =make_float2(acc[j][1][0],acc[j][1][1]);
            *(float2*)&ob[(size_t)(cc+8)*NN+n2]=make_float2(acc[j][1][2],acc[j][1][3]);
        }
    }
}

extern "C" void kernel_launch(void* const* d_in, const int* in_sizes, int n_in,
                              void* d_out, int out_size){
    const float* rgb=(const float*)d_in[0];
    const float* hsi=(const float*)d_in[1];
    const float* wq =(const float*)d_in[2];
    const float* wk =(const float*)d_in[3];
    const float* wv =(const float*)d_in[4];
    const float* wo =(const float*)d_in[5];
    float* out=(float*)d_out;

    cudaFuncSetAttribute(proj_kernel<0>, cudaFuncAttributeMaxDynamicSharedMemorySize, 2*PBUF);
    cudaFuncSetAttribute(proj_kernel<1>, cudaFuncAttributeMaxDynamicSharedMemorySize, 2*PBUF);
    cudaFuncSetAttribute(attn_kernel, cudaFuncAttributeMaxDynamicSharedMemorySize, 2*BUFB);
    prep_kernel<<<768,256>>>(wq,wk,wv,wo);
    proj_kernel<0><<<dim3(13,BB),256,2*PBUF>>>(rgb);
    proj_kernel<1><<<dim3(13,BB),256,2*PBUF>>>(hsi);
    attn_kernel<<<dim3(13,BB),256,2*BUFB>>>();
    out_kernel<<<dim3(13,4,BB),256,36864>>>(out);
}

// round 12
// speedup vs baseline: 1.9128x; 1.2426x over previous
#include <cuda_runtime.h>
#include <cuda_bf16.h>

#define BB 16
#define CC 512
#define NN 1600
#define NP 1664
#define HC 64
#define L2E8 0.1803368801111204f

typedef unsigned int u32; typedef unsigned short u16;

extern __shared__ __align__(16) unsigned char smdyn[];

// global scratch: bf16 hi/lo plane arrays
__device__ u16 g_Qh[BB*NP*HC], g_Ql[BB*NP*HC];   // Q [b][n][h]
__device__ u16 g_Kh[BB*NP*HC], g_Kl[BB*NP*HC];   // K [b][m][h]
__device__ u16 g_Vh[BB*HC*NP], g_Vl[BB*HC*NP];   // Vt [b][h][m]
__device__ u16 g_Rh[BB*HC*NP], g_Rl[BB*HC*NP];   // resT [b][h][n] flat == res2 [n'][k]
__device__ u16 g_Wh[3*HC*CC],  g_Wl[3*HC*CC];    // wT  [z][h][c] pitch 512
__device__ u16 g_Woh[CC*HC],   g_Wol[CC*HC];     // woT [c][k] pitch 64

__device__ __forceinline__ u32 pack_hl(float x){
    u32 h=__float_as_uint(x)&0xffff0000u; u16 lb;
    asm("cvt.rn.bf16.f32 %0,%1;":"=h"(lb):"f"(x-__uint_as_float(h)));
    return (h>>16)|((u32)lb<<16);
}
__device__ __forceinline__ void split2(float x0,float x1,u32& hi,u32& lo){
    u32 h0=__float_as_uint(x0)&0xffff0000u, h1=__float_as_uint(x1)&0xffff0000u;
    hi=(h0>>16)|h1;
    float l0=x0-__uint_as_float(h0), l1=x1-__uint_as_float(h1);
    asm("cvt.rn.bf16x2.f32 %0,%1,%2;":"=r"(lo):"f"(l1),"f"(l0));
}
__device__ __forceinline__ float ex2f(float x){float r;asm("ex2.approx.ftz.f32 %0,%1;":"=f"(r):"f"(x));return r;}
__device__ __forceinline__ u32 s2u(const void* p){u32 a;asm("{.reg .u64 t; cvta.to.shared.u64 t,%1; cvt.u32.u64 %0,t;}":"=r"(a):"l"(p));return a;}
__device__ __forceinline__ void mmabf(float (&c)[4], u32 a0,u32 a1,u32 a2,u32 a3, u32 b0,u32 b1){
    asm volatile("mma.sync.aligned.m16n8k16.row.col.f32.bf16.bf16.f32 "
        "{%0,%1,%2,%3},{%4,%5,%6,%7},{%8,%9},{%0,%1,%2,%3};"
        : "+f"(c[0]),"+f"(c[1]),"+f"(c[2]),"+f"(c[3])
        : "r"(a0),"r"(a1),"r"(a2),"r"(a3),"r"(b0),"r"(b1));
}
__device__ __forceinline__ void ldsm4(u32 (&r)[4], u32 a){
    asm volatile("ldmatrix.sync.aligned.m8n8.x4.shared.b16 {%0,%1,%2,%3},[%4];"
        :"=r"(r[0]),"=r"(r[1]),"=r"(r[2]),"=r"(r[3]):"r"(a));
}

// ---------------- prep ----------------
__global__ void prep_kernel(const float* __restrict__ wq,const float* __restrict__ wk,
                            const float* __restrict__ wv,const float* __restrict__ wo){
    int i=blockIdx.x*256+threadIdx.x;
    if(i<3*HC*CC){
        int z=i/(HC*CC), r=i%(HC*CC), h=r>>9, c=r&511;
        const float* p=(z==0)?wq:(z==1)?wk:wv;
        u32 v=pack_hl(p[c*HC+h]);
        g_Wh[i]=(u16)v; g_Wl[i]=(u16)(v>>16);
    } else if(i<3*HC*CC+CC*HC){
        int j=i-3*HC*CC, c=j>>6, k=j&63;
        u32 v=pack_hl(wo[k*CC+c]);
        g_Woh[j]=(u16)v; g_Wol[j]=(u16)(v>>16);
    } else {
        int j=i-(3*HC*CC+CC*HC);
        if(j<BB*4096){
            int b=j>>12, t=j&4095;
            size_t o=(size_t)b*HC*NP + HC*NN + t;
            g_Rh[o]=0; g_Rl[o]=0;
        }
    }
}

// ---------------- proj: 64-n tiles, mma.sync, 2 CTAs/SM ---------------------
// D[h][n] = wT[h][c] @ x[c][n].  A=wT (global), B=x^T [n][c] (smem, dbl-buf).
#define PBUF 18432     // one buffer: Xh(9216B) + Xl(9216B), 64n x 72c u16
template<int Z>
__global__ __launch_bounds__(256,2) void proj_kernel(const float* __restrict__ src_all){
    const int tid=threadIdx.x, lane=tid&31, w=tid>>5;
    const int n0=blockIdx.x*64, b=blockIdx.y;
    const float* src=src_all+(size_t)b*CC*NN;
    constexpr int NJS = Z? 2 : 4;
    const int sel = Z? 2 : (w>>2);
    const u16 *Ah_=g_Wh+sel*HC*CC, *Al_=g_Wl+sel*HC*CC;
    const int hf=w&3;
    const int jn0 = Z? (w>>2)*2 : 0;
    const u32 smb=s2u(smdyn);
    const int r4=lane>>2, c2=(lane&3)*2;
    const int mat=lane>>3, mr=((mat>>1)<<3)+(lane&7), hoff=(mat&1)<<3;
    float acc[NJS][2][4];
    #pragma unroll
    for(int j=0;j<NJS;j++)
        #pragma unroll
        for(int g=0;g<2;g++){acc[j][g][0]=0;acc[j][g][1]=0;acc[j][g][2]=0;acc[j][g][3]=0;}
    auto stage=[&](int ch,int buf){
        u16* Xh=(u16*)(smdyn+buf*PBUF); u16* Xl=(u16*)(smdyn+buf*PBUF+9216);
        int c0=ch*64;
        #pragma unroll
        for(int t=0;t<16;t++){
            int i=tid+t*256, c=i>>6, n=i&63;
            u32 v=pack_hl(src[(size_t)(c0+c)*NN+n0+n]);   // n0+n < 1600 always
            Xh[n*72+c]=(u16)v; Xl[n*72+c]=(u16)(v>>16);
        }
    };
    stage(0,0); __syncthreads();
    for(int ch=0;ch<8;ch++){
        const int bsel=ch&1;
        if(ch<7) stage(ch+1,bsel^1);
        const u32 kb=smb+bsel*PBUF;
        const int c0=ch*64;
        #pragma unroll
        for(int ks=0;ks<4;ks++){
            size_t o=(size_t)(hf*16+r4)*CC + c0+ks*16+c2;
            u32 a0h=*(const u32*)(Ah_+o),      a1h=*(const u32*)(Ah_+o+8*CC);
            u32 a2h=*(const u32*)(Ah_+o+8),    a3h=*(const u32*)(Ah_+o+8*CC+8);
            u32 a0l=*(const u32*)(Al_+o),      a1l=*(const u32*)(Al_+o+8*CC);
            u32 a2l=*(const u32*)(Al_+o+8),    a3l=*(const u32*)(Al_+o+8*CC+8);
            #pragma unroll
            for(int j=0;j<NJS;j++){
                u32 bh4[4],bl4[4];
                u32 a=kb+(((jn0+j)*16+mr)*72+ks*16+hoff)*2;
                ldsm4(bh4,a); ldsm4(bl4,a+9216);
                mmabf(acc[j][0],a0h,a1h,a2h,a3h,bh4[0],bh4[1]);
                mmabf(acc[j][1],a0h,a1h,a2h,a3h,bh4[2],bh4[3]);
                mmabf(acc[j][0],a0l,a1l,a2l,a3l,bh4[0],bh4[1]);
                mmabf(acc[j][1],a0l,a1l,a2l,a3l,bh4[2],bh4[3]);
                mmabf(acc[j][0],a0h,a1h,a2h,a3h,bl4[0],bl4[1]);
                mmabf(acc[j][1],a0h,a1h,a2h,a3h,bl4[2],bl4[3]);
            }
        }
        __syncthreads();
    }
    // epilogue via smem f32 tile [64h][67n]
    float* Of=(float*)smdyn;
    constexpr int NPASS=Z?1:2;
    for(int ps=0;ps<NPASS;ps++){
        if(Z || (w>>2)==ps){
            #pragma unroll
            for(int j=0;j<NJS;j++){
                int h=hf*16+r4, n=(jn0+j)*16+c2;
                Of[h*67+n]=acc[j][0][0];     Of[h*67+n+1]=acc[j][0][1];
                Of[(h+8)*67+n]=acc[j][0][2]; Of[(h+8)*67+n+1]=acc[j][0][3];
                Of[h*67+n+8]=acc[j][1][0];   Of[h*67+n+9]=acc[j][1][1];
                Of[(h+8)*67+n+8]=acc[j][1][2]; Of[(h+8)*67+n+9]=acc[j][1][3];
            }
        }
        __syncthreads();
        u16 *oh,*ol;
        if(Z){oh=g_Vh;ol=g_Vl;} else {oh=ps?g_Kh:g_Qh; ol=ps?g_Kl:g_Ql;}
        oh+=(size_t)b*NP*HC; ol+=(size_t)b*NP*HC;
        if(Z){   // Vt [h][m] pitch NP
            for(int i=tid;i<4096;i+=256){
                int h=i>>6, n=i&63;
                u32 v=pack_hl(Of[h*67+n]);
                oh[(size_t)h*NP+n0+n]=(u16)v; ol[(size_t)h*NP+n0+n]=(u16)(v>>16);
            }
        } else { // Q/K [n][h] pitch HC
            for(int i=tid;i<4096;i+=256){
                int n=i>>6, h=i&63;
                u32 v=pack_hl(Of[h*67+n]);
                oh[(size_t)(n0+n)*HC+h]=(u16)v; ol[(size_t)(n0+n)*HC+h]=(u16)(v>>16);
            }
        }
        __syncthreads();
    }
}

// ---------------- attn: FA2-style, fused PV, 2 CTAs/SM ----------------------
#define TILEB 9216
#define BUFB  36864
__global__ __launch_bounds__(256,2) void attn_kernel(){
    unsigned char* sm=smdyn;
    const int tid=threadIdx.x, lane=tid&31, warp=tid>>5;
    const int n0=blockIdx.x*128, b=blockIdx.y;
    const size_t qb=(size_t)b*NP*HC, vb=(size_t)b*HC*NP;
    const u16 *Qhp=g_Qh+qb,*Qlp=g_Ql+qb,*Khp=g_Kh+qb,*Klp=g_Kl+qb;
    const u16 *Vhp=g_Vh+vb,*Vlp=g_Vl+vb;
    const u32 smb=s2u(sm);
    const int q0=n0+warp*16, r4=lane>>2, c2=(lane&3)*2;
    u32 qh[4][4], ql[4][4];
    #pragma unroll
    for(int ks=0;ks<4;ks++){
        size_t o00=(size_t)(q0+r4)*HC+ks*16+c2, o10=o00+8*HC, o01=o00+8, o11=o10+8;
        qh[ks][0]=*(const u32*)(Qhp+o00); qh[ks][1]=*(const u32*)(Qhp+o10);
        qh[ks][2]=*(const u32*)(Qhp+o01); qh[ks][3]=*(const u32*)(Qhp+o11);
        ql[ks][0]=*(const u32*)(Qlp+o00); ql[ks][1]=*(const u32*)(Qlp+o10);
        ql[ks][2]=*(const u32*)(Qlp+o01); ql[ks][3]=*(const u32*)(Qlp+o11);
    }
    const int mat=lane>>3, mr=((mat>>1)<<3)+(lane&7), hoff=(mat&1)<<3;
    float O[8][4];
    #pragma unroll
    for(int j=0;j<8;j++){O[j][0]=0;O[j][1]=0;O[j][2]=0;O[j][3]=0;}
    float rsA=0.f, rsB=0.f;
    // vectorized tile loader: K[m][h] + Vt[h][m] hi/lo (each row 128B = 8 uint4)
    auto loadt=[&](int m0, unsigned char* buf){
        uint4* kh=(uint4*)buf; uint4* kl=(uint4*)(buf+TILEB);
        uint4* vh=(uint4*)(buf+2*TILEB); uint4* vl=(uint4*)(buf+3*TILEB);
        #pragma unroll
        for(int t=0;t<2;t++){
            int u=tid+t*256, r=u>>3, q=u&7;   // 64 rows x 8 uint4; smem pitch 9 uint4
            kh[r*9+q]=((const uint4*)(Khp+(size_t)(m0+r)*HC))[q];
            kl[r*9+q]=((const uint4*)(Klp+(size_t)(m0+r)*HC))[q];
            vh[r*9+q]=((const uint4*)(Vhp+(size_t)r*NP+m0))[q];
            vl[r*9+q]=((const uint4*)(Vlp+(size_t)r*NP+m0))[q];
        }
    };
    loadt(0, sm);
    __syncthreads();
    for(int it=0; it<25; it++){
        const int bsel=it&1;
        if(it<24) loadt((it+1)*64, sm+(bsel^1)*BUFB);
        const u32 kb=smb+bsel*BUFB;
        #pragma unroll
        for(int jj=0;jj<4;jj++){
            float c0[4]={0,0,0,0}, c1[4]={0,0,0,0};
            #pragma unroll
            for(int ks=0;ks<4;ks++){
                u32 kh4[4],kl4[4];
                u32 a=kb+(((jj*16+mr)*72)+ks*16+hoff)*2;
                ldsm4(kh4,a); ldsm4(kl4,a+TILEB);
                mmabf(c0,qh[ks][0],qh[ks][1],qh[ks][2],qh[ks][3],kh4[0],kh4[1]);
                mmabf(c1,qh[ks][0],qh[ks][1],qh[ks][2],qh[ks][3],kh4[2],kh4[3]);
                mmabf(c0,ql[ks][0],ql[ks][1],ql[ks][2],ql[ks][3],kh4[0],kh4[1]);
                mmabf(c1,ql[ks][0],ql[ks][1],ql[ks][2],ql[ks][3],kh4[2],kh4[3]);
                mmabf(c0,qh[ks][0],qh[ks][1],qh[ks][2],qh[ks][3],kl4[0],kl4[1]);
                mmabf(c1,qh[ks][0],qh[ks][1],qh[ks][2],qh[ks][3],kl4[2],kl4[3]);
            }
            #pragma unroll
            for(int e=0;e<4;e++){ c0[e]=ex2f(c0[e]*L2E8); c1[e]=ex2f(c1[e]*L2E8); }
            rsA += (c0[0]+c0[1])+(c1[0]+c1[1]);
            rsB += (c0[2]+c0[3])+(c1[2]+c1[3]);
            u32 Ph4[4], Pl4[4];
            split2(c0[0],c0[1],Ph4[0],Pl4[0]);
            split2(c0[2],c0[3],Ph4[1],Pl4[1]);
            split2(c1[0],c1[1],Ph4[2],Pl4[2]);
            split2(c1[2],c1[3],Ph4[3],Pl4[3]);
            #pragma unroll
            for(int hh=0;hh<4;hh++){
                u32 vh4[4],vl4[4];
                u32 a=kb+2*TILEB+(((hh*16+mr)*72)+jj*16+hoff)*2;
                ldsm4(vh4,a); ldsm4(vl4,a+TILEB);
                mmabf(O[hh*2],  Ph4[0],Ph4[1],Ph4[2],Ph4[3],vh4[0],vh4[1]);
                mmabf(O[hh*2+1],Ph4[0],Ph4[1],Ph4[2],Ph4[3],vh4[2],vh4[3]);
                mmabf(O[hh*2],  Pl4[0],Pl4[1],Pl4[2],Pl4[3],vh4[0],vh4[1]);
                mmabf(O[hh*2+1],Pl4[0],Pl4[1],Pl4[2],Pl4[3],vh4[2],vh4[3]);
                mmabf(O[hh*2],  Ph4[0],Ph4[1],Ph4[2],Ph4[3],vl4[0],vl4[1]);
                mmabf(O[hh*2+1],Ph4[0],Ph4[1],Ph4[2],Ph4[3],vl4[2],vl4[3]);
            }
        }
        __syncthreads();
    }
    rsA += __shfl_xor_sync(0xffffffffu,rsA,1); rsA += __shfl_xor_sync(0xffffffffu,rsA,2);
    rsB += __shfl_xor_sync(0xffffffffu,rsB,1); rsB += __shfl_xor_sync(0xffffffffu,rsB,2);
    const float invA=1.f/rsA, invB=1.f/rsB;
    float* Of=(float*)sm;
    #pragma unroll
    for(int j=0;j<8;j++){
        int h=j*8+c2;
        Of[(warp*16+r4)*68+h  ]=O[j][0]*invA;
        Of[(warp*16+r4)*68+h+1]=O[j][1]*invA;
        Of[(warp*16+r4+8)*68+h  ]=O[j][2]*invB;
        Of[(warp*16+r4+8)*68+h+1]=O[j][3]*invB;
    }
    __syncthreads();
    u16 *Rh=g_Rh+(size_t)b*HC*NP, *Rl=g_Rl+(size_t)b*HC*NP;
    for(int i=tid;i<8192;i+=256){
        int h=i>>7, n=i&127, gn=n0+n;
        if(gn<NN){
            u32 v=pack_hl(Of[n*68+h]);
            Rh[(size_t)h*NN+gn]=(u16)v; Rl[(size_t)h*NN+gn]=(u16)(v>>16);
        }
    }
}

// ---------------- out: mma.sync (unchanged) ---------------------------------
__global__ __launch_bounds__(256) void out_kernel(float* __restrict__ out){
    const int tid=threadIdx.x, lane=tid&31, w=tid>>5;
    const int n0=blockIdx.x*128, c0=blockIdx.y*128, b=blockIdx.z;
    const u32* sRh=(const u32*)(g_Rh+(size_t)b*HC*NP);
    const u32* sRl=(const u32*)(g_Rl+(size_t)b*HC*NP);
    u32* kh=(u32*)smdyn; u32* kl=(u32*)(smdyn+18432);
    #pragma unroll
    for(int t=0;t<16;t++){
        int i=tid+t*256, r=i>>5, ww=i&31;
        kh[r*36+ww]=sRh[(size_t)(n0+r)*32+ww];
        kl[r*36+ww]=sRl[(size_t)(n0+r)*32+ww];
    }
    __syncthreads();
    const u32 smb=s2u(smdyn);
    const int r4=lane>>2, c2=(lane&3)*2;
    const int mat=lane>>3, mr=((mat>>1)<<3)+(lane&7), hoff=(mat&1)<<3;
    float acc[8][2][4];
    #pragma unroll
    for(int j=0;j<8;j++)
        #pragma unroll
        for(int g=0;g<2;g++){acc[j][g][0]=0;acc[j][g][1]=0;acc[j][g][2]=0;acc[j][g][3]=0;}
    #pragma unroll
    for(int ks=0;ks<4;ks++){
        size_t o=(size_t)(c0+w*16+r4)*HC + ks*16+c2;
        u32 a0h=*(const u32*)(g_Woh+o),   a1h=*(const u32*)(g_Woh+o+8*HC);
        u32 a2h=*(const u32*)(g_Woh+o+8), a3h=*(const u32*)(g_Woh+o+8*HC+8);
        u32 a0l=*(const u32*)(g_Wol+o),   a1l=*(const u32*)(g_Wol+o+8*HC);
        u32 a2l=*(const u32*)(g_Wol+o+8), a3l=*(const u32*)(g_Wol+o+8*HC+8);
        #pragma unroll
        for(int j=0;j<8;j++){
            u32 bh4[4],bl4[4];
            u32 a=smb+((j*16+mr)*72+ks*16+hoff)*2;
            ldsm4(bh4,a); ldsm4(bl4,a+18432);
            mmabf(acc[j][0],a0h,a1h,a2h,a3h,bh4[0],bh4[1]);
            mmabf(acc[j][1],a0h,a1h,a2h,a3h,bh4[2],bh4[3]);
            mmabf(acc[j][0],a0l,a1l,a2l,a3l,bh4[0],bh4[1]);
            mmabf(acc[j][1],a0l,a1l,a2l,a3l,bh4[2],bh4[3]);
            mmabf(acc[j][0],a0h,a1h,a2h,a3h,bl4[0],bl4[1]);
            mmabf(acc[j][1],a0h,a1h,a2h,a3h,bl4[2],bl4[3]);
        }
    }
    float* ob=out+(size_t)b*CC*NN;
    const int cc=c0+w*16+r4;
    #pragma unroll
    for(int j=0;j<8;j++){
        int nn=n0+j*16+c2;
        if(nn<NN){
            *(float2*)&ob[(size_t)cc*NN+nn]    =make_float2(acc[j][0][0],acc[j][0][1]);
            *(float2*)&ob[(size_t)(cc+8)*NN+nn]=make_float2(acc[j][0][2],acc[j][0][3]);
        }
        int n2=nn+8;
        if(n2<NN){
            *(float2*)&ob[(size_t)cc*NN+n2]    =make_float2(acc[j][1][0],acc[j][1][1]);
            *(float2*)&ob[(size_t)(cc+8)*NN+n2]=make_float2(acc[j][1][2],acc[j][1][3]);
        }
    }
}

extern "C" void kernel_launch(void* const* d_in, const int* in_sizes, int n_in,
                              void* d_out, int out_size){
    const float* rgb=(const float*)d_in[0];
    const float* hsi=(const float*)d_in[1];
    const float* wq =(const float*)d_in[2];
    const float* wk =(const float*)d_in[3];
    const float* wv =(const float*)d_in[4];
    const float* wo =(const float*)d_in[5];
    float* out=(float*)d_out;

    cudaFuncSetAttribute(proj_kernel<0>, cudaFuncAttributeMaxDynamicSharedMemorySize, 2*PBUF);
    cudaFuncSetAttribute(proj_kernel<1>, cudaFuncAttributeMaxDynamicSharedMemorySize, 2*PBUF);
    cudaFuncSetAttribute(attn_kernel, cudaFuncAttributeMaxDynamicSharedMemorySize, 2*BUFB);
    prep_kernel<<<768,256>>>(wq,wk,wv,wo);
    proj_kernel<0><<<dim3(25,BB),256,2*PBUF>>>(rgb);
    proj_kernel<1><<<dim3(25,BB),256,2*PBUF>>>(hsi);
    attn_kernel<<<dim3(13,BB),256,2*BUFB>>>();
    out_kernel<<<dim3(13,4,BB),256,36864>>>(out);
}

// round 13
// speedup vs baseline: 2.0880x; 1.0916x over previous
#include <cuda_runtime.h>
#include <cuda_bf16.h>

#define BB 16
#define CC 512
#define NN 1600
#define NP 1664
#define HC 64
#define L2E8 0.1803368801111204f

typedef unsigned int u32; typedef unsigned short u16;

extern __shared__ __align__(16) unsigned char smdyn[];

// global scratch: bf16 hi/lo plane arrays
__device__ u16 g_Qh[BB*NP*HC], g_Ql[BB*NP*HC];   // Q [b][n][h]
__device__ u16 g_Kh[BB*NP*HC], g_Kl[BB*NP*HC];   // K [b][m][h]
__device__ u16 g_Vh[BB*HC*NP], g_Vl[BB*HC*NP];   // Vt [b][h][m]
__device__ u16 g_Rh[BB*HC*NP], g_Rl[BB*HC*NP];   // resT [b][h][n] flat == res2 [n'][k]
__device__ u16 g_Wh[3*HC*CC],  g_Wl[3*HC*CC];    // wT  [z][h][c] pitch 512
__device__ u16 g_Woh[CC*HC],   g_Wol[CC*HC];     // woT [c][k] pitch 64

__device__ __forceinline__ u32 pack_hl(float x){
    u32 h=__float_as_uint(x)&0xffff0000u; u16 lb;
    asm("cvt.rn.bf16.f32 %0,%1;":"=h"(lb):"f"(x-__uint_as_float(h)));
    return (h>>16)|((u32)lb<<16);
}
__device__ __forceinline__ void split2(float x0,float x1,u32& hi,u32& lo){
    u32 h0=__float_as_uint(x0)&0xffff0000u, h1=__float_as_uint(x1)&0xffff0000u;
    hi=(h0>>16)|h1;
    float l0=x0-__uint_as_float(h0), l1=x1-__uint_as_float(h1);
    asm("cvt.rn.bf16x2.f32 %0,%1,%2;":"=r"(lo):"f"(l1),"f"(l0));
}
__device__ __forceinline__ float ex2f(float x){float r;asm("ex2.approx.ftz.f32 %0,%1;":"=f"(r):"f"(x));return r;}
__device__ __forceinline__ u32 s2u(const void* p){u32 a;asm("{.reg .u64 t; cvta.to.shared.u64 t,%1; cvt.u32.u64 %0,t;}":"=r"(a):"l"(p));return a;}
__device__ __forceinline__ void mmabf(float (&c)[4], u32 a0,u32 a1,u32 a2,u32 a3, u32 b0,u32 b1){
    asm volatile("mma.sync.aligned.m16n8k16.row.col.f32.bf16.bf16.f32 "
        "{%0,%1,%2,%3},{%4,%5,%6,%7},{%8,%9},{%0,%1,%2,%3};"
        : "+f"(c[0]),"+f"(c[1]),"+f"(c[2]),"+f"(c[3])
        : "r"(a0),"r"(a1),"r"(a2),"r"(a3),"r"(b0),"r"(b1));
}
__device__ __forceinline__ void ldsm4(u32 (&r)[4], u32 a){
    asm volatile("ldmatrix.sync.aligned.m8n8.x4.shared.b16 {%0,%1,%2,%3},[%4];"
        :"=r"(r[0]),"=r"(r[1]),"=r"(r[2]),"=r"(r[3]):"r"(a));
}
__device__ __forceinline__ void cpa16(u32 saddr, const void* g){
    asm volatile("cp.async.ca.shared.global [%0], [%1], 16;"::"r"(saddr),"l"(g));
}

// ---------------- prep ----------------
__global__ void prep_kernel(const float* __restrict__ wq,const float* __restrict__ wk,
                            const float* __restrict__ wv,const float* __restrict__ wo){
    int i=blockIdx.x*256+threadIdx.x;
    if(i<3*HC*CC){
        int z=i/(HC*CC), r=i%(HC*CC), h=r>>9, c=r&511;
        const float* p=(z==0)?wq:(z==1)?wk:wv;
        u32 v=pack_hl(p[c*HC+h]);
        g_Wh[i]=(u16)v; g_Wl[i]=(u16)(v>>16);
    } else if(i<3*HC*CC+CC*HC){
        int j=i-3*HC*CC, c=j>>6, k=j&63;
        u32 v=pack_hl(wo[k*CC+c]);
        g_Woh[j]=(u16)v; g_Wol[j]=(u16)(v>>16);
    } else {
        int j=i-(3*HC*CC+CC*HC);
        if(j<BB*4096){
            int b=j>>12, t=j&4095;
            size_t o=(size_t)b*HC*NP + HC*NN + t;
            g_Rh[o]=0; g_Rl[o]=0;
        }
    }
}

// ---------------- proj: 64-n tiles, mma.sync, 2 CTAs/SM (unchanged) ---------
#define PBUF 18432
template<int Z>
__global__ __launch_bounds__(256,2) void proj_kernel(const float* __restrict__ src_all){
    const int tid=threadIdx.x, lane=tid&31, w=tid>>5;
    const int n0=blockIdx.x*64, b=blockIdx.y;
    const float* src=src_all+(size_t)b*CC*NN;
    constexpr int NJS = Z? 2 : 4;
    const int sel = Z? 2 : (w>>2);
    const u16 *Ah_=g_Wh+sel*HC*CC, *Al_=g_Wl+sel*HC*CC;
    const int hf=w&3;
    const int jn0 = Z? (w>>2)*2 : 0;
    const u32 smb=s2u(smdyn);
    const int r4=lane>>2, c2=(lane&3)*2;
    const int mat=lane>>3, mr=((mat>>1)<<3)+(lane&7), hoff=(mat&1)<<3;
    float acc[NJS][2][4];
    #pragma unroll
    for(int j=0;j<NJS;j++)
        #pragma unroll
        for(int g=0;g<2;g++){acc[j][g][0]=0;acc[j][g][1]=0;acc[j][g][2]=0;acc[j][g][3]=0;}
    auto stage=[&](int ch,int buf){
        u16* Xh=(u16*)(smdyn+buf*PBUF); u16* Xl=(u16*)(smdyn+buf*PBUF+9216);
        int c0=ch*64;
        #pragma unroll
        for(int t=0;t<16;t++){
            int i=tid+t*256, c=i>>6, n=i&63;
            u32 v=pack_hl(src[(size_t)(c0+c)*NN+n0+n]);
            Xh[n*72+c]=(u16)v; Xl[n*72+c]=(u16)(v>>16);
        }
    };
    stage(0,0); __syncthreads();
    for(int ch=0;ch<8;ch++){
        const int bsel=ch&1;
        if(ch<7) stage(ch+1,bsel^1);
        const u32 kb=smb+bsel*PBUF;
        const int c0=ch*64;
        #pragma unroll
        for(int ks=0;ks<4;ks++){
            size_t o=(size_t)(hf*16+r4)*CC + c0+ks*16+c2;
            u32 a0h=*(const u32*)(Ah_+o),      a1h=*(const u32*)(Ah_+o+8*CC);
            u32 a2h=*(const u32*)(Ah_+o+8),    a3h=*(const u32*)(Ah_+o+8*CC+8);
            u32 a0l=*(const u32*)(Al_+o),      a1l=*(const u32*)(Al_+o+8*CC);
            u32 a2l=*(const u32*)(Al_+o+8),    a3l=*(const u32*)(Al_+o+8*CC+8);
            #pragma unroll
            for(int j=0;j<NJS;j++){
                u32 bh4[4],bl4[4];
                u32 a=kb+(((jn0+j)*16+mr)*72+ks*16+hoff)*2;
                ldsm4(bh4,a); ldsm4(bl4,a+9216);
                mmabf(acc[j][0],a0h,a1h,a2h,a3h,bh4[0],bh4[1]);
                mmabf(acc[j][1],a0h,a1h,a2h,a3h,bh4[2],bh4[3]);
                mmabf(acc[j][0],a0l,a1l,a2l,a3l,bh4[0],bh4[1]);
                mmabf(acc[j][1],a0l,a1l,a2l,a3l,bh4[2],bh4[3]);
                mmabf(acc[j][0],a0h,a1h,a2h,a3h,bl4[0],bl4[1]);
                mmabf(acc[j][1],a0h,a1h,a2h,a3h,bl4[2],bl4[3]);
            }
        }
        __syncthreads();
    }
    float* Of=(float*)smdyn;
    constexpr int NPASS=Z?1:2;
    for(int ps=0;ps<NPASS;ps++){
        if(Z || (w>>2)==ps){
            #pragma unroll
            for(int j=0;j<NJS;j++){
                int h=hf*16+r4, n=(jn0+j)*16+c2;
                Of[h*67+n]=acc[j][0][0];     Of[h*67+n+1]=acc[j][0][1];
                Of[(h+8)*67+n]=acc[j][0][2]; Of[(h+8)*67+n+1]=acc[j][0][3];
                Of[h*67+n+8]=acc[j][1][0];   Of[h*67+n+9]=acc[j][1][1];
                Of[(h+8)*67+n+8]=acc[j][1][2]; Of[(h+8)*67+n+9]=acc[j][1][3];
            }
        }
        __syncthreads();
        u16 *oh,*ol;
        if(Z){oh=g_Vh;ol=g_Vl;} else {oh=ps?g_Kh:g_Qh; ol=ps?g_Kl:g_Ql;}
        oh+=(size_t)b*NP*HC; ol+=(size_t)b*NP*HC;
        if(Z){
            for(int i=tid;i<4096;i+=256){
                int h=i>>6, n=i&63;
                u32 v=pack_hl(Of[h*67+n]);
                oh[(size_t)h*NP+n0+n]=(u16)v; ol[(size_t)h*NP+n0+n]=(u16)(v>>16);
            }
        } else {
            for(int i=tid;i<4096;i+=256){
                int n=i>>6, h=i&63;
                u32 v=pack_hl(Of[h*67+n]);
                oh[(size_t)(n0+n)*HC+h]=(u16)v; ol[(size_t)(n0+n)*HC+h]=(u16)(v>>16);
            }
        }
        __syncthreads();
    }
}

// ---------------- attn: 64q CTAs, jj-split warp pairs, cp.async -------------
#define TILEB 9216
#define BUFB  36864
__global__ __launch_bounds__(256,2) void attn_kernel(){
    unsigned char* sm=smdyn;
    const int tid=threadIdx.x, lane=tid&31, warp=tid>>5;
    const int n0=blockIdx.x*64, b=blockIdx.y;
    const size_t qb=(size_t)b*NP*HC, vb=(size_t)b*HC*NP;
    const u16 *Qhp=g_Qh+qb,*Qlp=g_Ql+qb,*Khp=g_Kh+qb,*Klp=g_Kl+qb;
    const u16 *Vhp=g_Vh+vb,*Vlp=g_Vl+vb;
    const u32 smb=s2u(sm);
    const int qsub=warp&3, jj0=(warp>>2)*2;       // warp pair split over key cols
    const int q0=n0+qsub*16, r4=lane>>2, c2=(lane&3)*2;
    u32 qh[4][4], ql[4][4];
    #pragma unroll
    for(int ks=0;ks<4;ks++){
        size_t o00=(size_t)(q0+r4)*HC+ks*16+c2, o10=o00+8*HC, o01=o00+8, o11=o10+8;
        qh[ks][0]=*(const u32*)(Qhp+o00); qh[ks][1]=*(const u32*)(Qhp+o10);
        qh[ks][2]=*(const u32*)(Qhp+o01); qh[ks][3]=*(const u32*)(Qhp+o11);
        ql[ks][0]=*(const u32*)(Qlp+o00); ql[ks][1]=*(const u32*)(Qlp+o10);
        ql[ks][2]=*(const u32*)(Qlp+o01); ql[ks][3]=*(const u32*)(Qlp+o11);
    }
    const int mat=lane>>3, mr=((mat>>1)<<3)+(lane&7), hoff=(mat&1)<<3;
    float O[8][4];
    #pragma unroll
    for(int j=0;j<8;j++){O[j][0]=0;O[j][1]=0;O[j][2]=0;O[j][3]=0;}
    float rsA=0.f, rsB=0.f;
    // async tile staging: K[m][h] + Vt[h][m] hi/lo (64 rows x 8 uint4, pitch 9)
    auto stage=[&](int m0, int buf){
        u32 ba=smb+buf*BUFB;
        #pragma unroll
        for(int t=0;t<2;t++){
            int u=tid+t*256, r=u>>3, q=u&7;
            u32 so=(u32)(r*9+q)*16;
            cpa16(ba+so,         Khp+(size_t)(m0+r)*HC+q*8);
            cpa16(ba+TILEB+so,   Klp+(size_t)(m0+r)*HC+q*8);
            cpa16(ba+2*TILEB+so, Vhp+(size_t)r*NP+m0+q*8);
            cpa16(ba+3*TILEB+so, Vlp+(size_t)r*NP+m0+q*8);
        }
        asm volatile("cp.async.commit_group;":::"memory");
    };
    stage(0,0);
    asm volatile("cp.async.wait_group 0;":::"memory");
    __syncthreads();
    for(int it=0; it<25; it++){
        const int bsel=it&1;
        if(it<24) stage((it+1)*64, bsel^1);
        const u32 kb=smb+bsel*BUFB;
        #pragma unroll
        for(int jj=0;jj<2;jj++){
            const int j=jj0+jj;
            float c0[4]={0,0,0,0}, c1[4]={0,0,0,0};
            #pragma unroll
            for(int ks=0;ks<4;ks++){
                u32 kh4[4],kl4[4];
                u32 a=kb+(((j*16+mr)*72)+ks*16+hoff)*2;
                ldsm4(kh4,a); ldsm4(kl4,a+TILEB);
                mmabf(c0,qh[ks][0],qh[ks][1],qh[ks][2],qh[ks][3],kh4[0],kh4[1]);
                mmabf(c1,qh[ks][0],qh[ks][1],qh[ks][2],qh[ks][3],kh4[2],kh4[3]);
                mmabf(c0,ql[ks][0],ql[ks][1],ql[ks][2],ql[ks][3],kh4[0],kh4[1]);
                mmabf(c1,ql[ks][0],ql[ks][1],ql[ks][2],ql[ks][3],kh4[2],kh4[3]);
                mmabf(c0,qh[ks][0],qh[ks][1],qh[ks][2],qh[ks][3],kl4[0],kl4[1]);
                mmabf(c1,qh[ks][0],qh[ks][1],qh[ks][2],qh[ks][3],kl4[2],kl4[3]);
            }
            #pragma unroll
            for(int e=0;e<4;e++){ c0[e]=ex2f(c0[e]*L2E8); c1[e]=ex2f(c1[e]*L2E8); }
            rsA += (c0[0]+c0[1])+(c1[0]+c1[1]);
            rsB += (c0[2]+c0[3])+(c1[2]+c1[3]);
            u32 Ph4[4], Pl4[4];
            split2(c0[0],c0[1],Ph4[0],Pl4[0]);
            split2(c0[2],c0[3],Ph4[1],Pl4[1]);
            split2(c1[0],c1[1],Ph4[2],Pl4[2]);
            split2(c1[2],c1[3],Ph4[3],Pl4[3]);
            #pragma unroll
            for(int hh=0;hh<4;hh++){
                u32 vh4[4],vl4[4];
                u32 a=kb+2*TILEB+(((hh*16+mr)*72)+j*16+hoff)*2;
                ldsm4(vh4,a); ldsm4(vl4,a+TILEB);
                mmabf(O[hh*2],  Ph4[0],Ph4[1],Ph4[2],Ph4[3],vh4[0],vh4[1]);
                mmabf(O[hh*2+1],Ph4[0],Ph4[1],Ph4[2],Ph4[3],vh4[2],vh4[3]);
                mmabf(O[hh*2],  Pl4[0],Pl4[1],Pl4[2],Pl4[3],vh4[0],vh4[1]);
                mmabf(O[hh*2+1],Pl4[0],Pl4[1],Pl4[2],Pl4[3],vh4[2],vh4[3]);
                mmabf(O[hh*2],  Ph4[0],Ph4[1],Ph4[2],Ph4[3],vl4[0],vl4[1]);
                mmabf(O[hh*2+1],Ph4[0],Ph4[1],Ph4[2],Ph4[3],vl4[2],vl4[3]);
            }
        }
        asm volatile("cp.async.wait_group 0;":::"memory");
        __syncthreads();
    }
    // reduce row-sums within quad
    rsA += __shfl_xor_sync(0xffffffffu,rsA,1); rsA += __shfl_xor_sync(0xffffffffu,rsA,2);
    rsB += __shfl_xor_sync(0xffffffffu,rsB,1); rsB += __shfl_xor_sync(0xffffffffu,rsB,2);
    // combine warp pairs (group B -> smem, group A adds)
    float* Po=(float*)sm;                 // 16384 B
    float* Rs=(float*)(sm+16384);         // 1024 B
    float* Of=(float*)(sm+17664);         // 64 x 68 f32
    if(warp>=4){
        int base=(qsub*32+lane)*32;
        #pragma unroll
        for(int j=0;j<8;j++)
            #pragma unroll
            for(int e=0;e<4;e++) Po[base+j*4+e]=O[j][e];
        Rs[(qsub*32+lane)*2+0]=rsA;
        Rs[(qsub*32+lane)*2+1]=rsB;
    }
    __syncthreads();
    if(warp<4){
        int base=(qsub*32+lane)*32;
        #pragma unroll
        for(int j=0;j<8;j++)
            #pragma unroll
            for(int e=0;e<4;e++) O[j][e]+=Po[base+j*4+e];
        rsA+=Rs[(qsub*32+lane)*2+0];
        rsB+=Rs[(qsub*32+lane)*2+1];
        const float invA=1.f/rsA, invB=1.f/rsB;
        #pragma unroll
        for(int j=0;j<8;j++){
            int h=j*8+c2;
            Of[(qsub*16+r4)*68+h  ]=O[j][0]*invA;
            Of[(qsub*16+r4)*68+h+1]=O[j][1]*invA;
            Of[(qsub*16+r4+8)*68+h  ]=O[j][2]*invB;
            Of[(qsub*16+r4+8)*68+h+1]=O[j][3]*invB;
        }
    }
    __syncthreads();
    u16 *Rh=g_Rh+(size_t)b*HC*NP, *Rl=g_Rl+(size_t)b*HC*NP;
    for(int i=tid;i<4096;i+=256){
        int h=i>>6, n=i&63, gn=n0+n;
        u32 v=pack_hl(Of[n*68+h]);
        Rh[(size_t)h*NN+gn]=(u16)v; Rl[(size_t)h*NN+gn]=(u16)(v>>16);
    }
}

// ---------------- out: mma.sync (unchanged) ---------------------------------
__global__ __launch_bounds__(256) void out_kernel(float* __restrict__ out){
    const int tid=threadIdx.x, lane=tid&31, w=tid>>5;
    const int n0=blockIdx.x*128, c0=blockIdx.y*128, b=blockIdx.z;
    const u32* sRh=(const u32*)(g_Rh+(size_t)b*HC*NP);
    const u32* sRl=(const u32*)(g_Rl+(size_t)b*HC*NP);
    u32* kh=(u32*)smdyn; u32* kl=(u32*)(smdyn+18432);
    #pragma unroll
    for(int t=0;t<16;t++){
        int i=tid+t*256, r=i>>5, ww=i&31;
        kh[r*36+ww]=sRh[(size_t)(n0+r)*32+ww];
        kl[r*36+ww]=sRl[(size_t)(n0+r)*32+ww];
    }
    __syncthreads();
    const u32 smb=s2u(smdyn);
    const int r4=lane>>2, c2=(lane&3)*2;
    const int mat=lane>>3, mr=((mat>>1)<<3)+(lane&7), hoff=(mat&1)<<3;
    float acc[8][2][4];
    #pragma unroll
    for(int j=0;j<8;j++)
        #pragma unroll
        for(int g=0;g<2;g++){acc[j][g][0]=0;acc[j][g][1]=0;acc[j][g][2]=0;acc[j][g][3]=0;}
    #pragma unroll
    for(int ks=0;ks<4;ks++){
        size_t o=(size_t)(c0+w*16+r4)*HC + ks*16+c2;
        u32 a0h=*(const u32*)(g_Woh+o),   a1h=*(const u32*)(g_Woh+o+8*HC);
        u32 a2h=*(const u32*)(g_Woh+o+8), a3h=*(const u32*)(g_Woh+o+8*HC+8);
        u32 a0l=*(const u32*)(g_Wol+o),   a1l=*(const u32*)(g_Wol+o+8*HC);
        u32 a2l=*(const u32*)(g_Wol+o+8), a3l=*(const u32*)(g_Wol+o+8*HC+8);
        #pragma unroll
        for(int j=0;j<8;j++){
            u32 bh4[4],bl4[4];
            u32 a=smb+((j*16+mr)*72+ks*16+hoff)*2;
            ldsm4(bh4,a); ldsm4(bl4,a+18432);
            mmabf(acc[j][0],a0h,a1h,a2h,a3h,bh4[0],bh4[1]);
            mmabf(acc[j][1],a0h,a1h,a2h,a3h,bh4[2],bh4[3]);
            mmabf(acc[j][0],a0l,a1l,a2l,a3l,bh4[0],bh4[1]);
            mmabf(acc[j][1],a0l,a1l,a2l,a3l,bh4[2],bh4[3]);
            mmabf(acc[j][0],a0h,a1h,a2h,a3h,bl4[0],bl4[1]);
            mmabf(acc[j][1],a0h,a1h,a2h,a3h,bl4[2],bl4[3]);
        }
    }
    float* ob=out+(size_t)b*CC*NN;
    const int cc=c0+w*16+r4;
    #pragma unroll
    for(int j=0;j<8;j++){
        int nn=n0+j*16+c2;
        if(nn<NN){
            *(float2*)&ob[(size_t)cc*NN+nn]    =make_float2(acc[j][0][0],acc[j][0][1]);
            *(float2*)&ob[(size_t)(cc+8)*NN+nn]=make_float2(acc[j][0][2],acc[j][0][3]);
        }
        int n2=nn+8;
        if(n2<NN){
            *(float2*)&ob[(size_t)cc*NN+n2]    =make_float2(acc[j][1][0],acc[j][1][1]);
            *(float2*)&ob[(size_t)(cc+8)*NN+n2]=make_float2(acc[j][1][2],acc[j][1][3]);
        }
    }
}

extern "C" void kernel_launch(void* const* d_in, const int* in_sizes, int n_in,
                              void* d_out, int out_size){
    const float* rgb=(const float*)d_in[0];
    const float* hsi=(const float*)d_in[1];
    const float* wq =(const float*)d_in[2];
    const float* wk =(const float*)d_in[3];
    const float* wv =(const float*)d_in[4];
    const float* wo =(const float*)d_in[5];
    float* out=(float*)d_out;

    cudaFuncSetAttribute(proj_kernel<0>, cudaFuncAttributeMaxDynamicSharedMemorySize, 2*PBUF);
    cudaFuncSetAttribute(proj_kernel<1>, cudaFuncAttributeMaxDynamicSharedMemorySize, 2*PBUF);
    cudaFuncSetAttribute(attn_kernel, cudaFuncAttributeMaxDynamicSharedMemorySize, 2*BUFB);
    prep_kernel<<<768,256>>>(wq,wk,wv,wo);
    proj_kernel<0><<<dim3(25,BB),256,2*PBUF>>>(rgb);
    proj_kernel<1><<<dim3(25,BB),256,2*PBUF>>>(hsi);
    attn_kernel<<<dim3(25,BB),256,2*BUFB>>>();
    out_kernel<<<dim3(13,4,BB),256,36864>>>(out);
}

// round 15
// speedup vs baseline: 2.2795x; 1.0917x over previous
#include <cuda_runtime.h>
#include <cuda_bf16.h>

#define BB 16
#define CC 512
#define NN 1600
#define NP 1664
#define HC 64
#define L2E8 0.1803368801111204f

typedef unsigned int u32; typedef unsigned short u16;

extern __shared__ __align__(16) unsigned char smdyn[];

// global scratch: bf16 hi/lo plane arrays
__device__ u16 g_Qh[BB*NP*HC], g_Ql[BB*NP*HC];   // Q [b][n][h]
__device__ u16 g_Kh[BB*NP*HC], g_Kl[BB*NP*HC];   // K [b][m][h]
__device__ u16 g_Vh[BB*HC*NP], g_Vl[BB*HC*NP];   // Vt [b][h][m]
__device__ u16 g_Rh[BB*HC*NP], g_Rl[BB*HC*NP];   // resT [b][h][n] flat == res2 [n'][k]
__device__ u16 g_Wh[3*HC*CC],  g_Wl[3*HC*CC];    // wT  [z][h][c] pitch 512
__device__ u16 g_Woh[CC*HC],   g_Wol[CC*HC];     // woT [c][k] pitch 64

__device__ __forceinline__ u32 pack_hl(float x){
    u32 h=__float_as_uint(x)&0xffff0000u; u16 lb;
    asm("cvt.rn.bf16.f32 %0,%1;":"=h"(lb):"f"(x-__uint_as_float(h)));
    return (h>>16)|((u32)lb<<16);
}
__device__ __forceinline__ void split2(float x0,float x1,u32& hi,u32& lo){
    u32 h0=__float_as_uint(x0)&0xffff0000u, h1=__float_as_uint(x1)&0xffff0000u;
    hi=(h0>>16)|h1;
    float l0=x0-__uint_as_float(h0), l1=x1-__uint_as_float(h1);
    asm("cvt.rn.bf16x2.f32 %0,%1,%2;":"=r"(lo):"f"(l1),"f"(l0));
}
__device__ __forceinline__ float ex2f(float x){float r;asm("ex2.approx.ftz.f32 %0,%1;":"=f"(r):"f"(x));return r;}
__device__ __forceinline__ u32 s2u(const void* p){u32 a;asm("{.reg .u64 t; cvta.to.shared.u64 t,%1; cvt.u32.u64 %0,t;}":"=r"(a):"l"(p));return a;}
__device__ __forceinline__ void mmabf(float (&c)[4], u32 a0,u32 a1,u32 a2,u32 a3, u32 b0,u32 b1){
    asm volatile("mma.sync.aligned.m16n8k16.row.col.f32.bf16.bf16.f32 "
        "{%0,%1,%2,%3},{%4,%5,%6,%7},{%8,%9},{%0,%1,%2,%3};"
        : "+f"(c[0]),"+f"(c[1]),"+f"(c[2]),"+f"(c[3])
        : "r"(a0),"r"(a1),"r"(a2),"r"(a3),"r"(b0),"r"(b1));
}
__device__ __forceinline__ void ldsm4(u32 (&r)[4], u32 a){
    asm volatile("ldmatrix.sync.aligned.m8n8.x4.shared.b16 {%0,%1,%2,%3},[%4];"
        :"=r"(r[0]),"=r"(r[1]),"=r"(r[2]),"=r"(r[3]):"r"(a));
}
__device__ __forceinline__ void cpa16(u32 saddr, const void* g){
    asm volatile("cp.async.ca.shared.global [%0], [%1], 16;"::"r"(saddr),"l"(g));
}

// ---------------- prep (512 blocks x 256 = 131072 threads exactly) ----------
__global__ void prep_kernel(const float* __restrict__ wq,const float* __restrict__ wk,
                            const float* __restrict__ wv,const float* __restrict__ wo){
    int i=blockIdx.x*256+threadIdx.x;
    if(i<3*HC*CC){
        int z=i/(HC*CC), r=i%(HC*CC), h=r>>9, c=r&511;
        const float* p=(z==0)?wq:(z==1)?wk:wv;
        u32 v=pack_hl(p[c*HC+h]);
        g_Wh[i]=(u16)v; g_Wl[i]=(u16)(v>>16);
    } else {
        int j=i-3*HC*CC, c=j>>6, k=j&63;
        u32 v=pack_hl(wo[k*CC+c]);
        g_Woh[j]=(u16)v; g_Wol[j]=(u16)(v>>16);
    }
}

// ---------------- proj body: templated, fully unrolled -----------------------
#define PBUF 18432
template<int Z>
__device__ __forceinline__ void proj_body(const float* __restrict__ src_all){
    const int tid=threadIdx.x, lane=tid&31, w=tid>>5;
    const int n0=blockIdx.x*64, b=blockIdx.y;
    const float* src=src_all+(size_t)b*CC*NN;
    constexpr int NJS = Z? 2 : 4;
    const int sel = Z? 2 : (w>>2);
    const u16 *Ah_=g_Wh+sel*HC*CC, *Al_=g_Wl+sel*HC*CC;
    const int hf=w&3;
    const int jn0 = Z? (w>>2)*2 : 0;
    const u32 smb=s2u(smdyn);
    const int r4=lane>>2, c2=(lane&3)*2;
    const int mat=lane>>3, mr=((mat>>1)<<3)+(lane&7), hoff=(mat&1)<<3;
    float acc[NJS][2][4];
    #pragma unroll
    for(int j=0;j<NJS;j++)
        #pragma unroll
        for(int g=0;g<2;g++){acc[j][g][0]=0;acc[j][g][1]=0;acc[j][g][2]=0;acc[j][g][3]=0;}
    auto stage=[&](int ch,int buf){
        u16* Xh=(u16*)(smdyn+buf*PBUF); u16* Xl=(u16*)(smdyn+buf*PBUF+9216);
        int c0=ch*64;
        #pragma unroll
        for(int t=0;t<16;t++){
            int i=tid+t*256, c=i>>6, n=i&63;
            u32 v=pack_hl(src[(size_t)(c0+c)*NN+n0+n]);
            Xh[n*72+c]=(u16)v; Xl[n*72+c]=(u16)(v>>16);
        }
    };
    stage(0,0); __syncthreads();
    for(int ch=0;ch<8;ch++){
        const int bsel=ch&1;
        if(ch<7) stage(ch+1,bsel^1);
        const u32 kb=smb+bsel*PBUF;
        const int c0=ch*64;
        #pragma unroll
        for(int ks=0;ks<4;ks++){
            size_t o=(size_t)(hf*16+r4)*CC + c0+ks*16+c2;
            u32 a0h=*(const u32*)(Ah_+o),      a1h=*(const u32*)(Ah_+o+8*CC);
            u32 a2h=*(const u32*)(Ah_+o+8),    a3h=*(const u32*)(Ah_+o+8*CC+8);
            u32 a0l=*(const u32*)(Al_+o),      a1l=*(const u32*)(Al_+o+8*CC);
            u32 a2l=*(const u32*)(Al_+o+8),    a3l=*(const u32*)(Al_+o+8*CC+8);
            #pragma unroll
            for(int j=0;j<NJS;j++){
                u32 bh4[4],bl4[4];
                u32 a=kb+(((jn0+j)*16+mr)*72+ks*16+hoff)*2;
                ldsm4(bh4,a); ldsm4(bl4,a+9216);
                mmabf(acc[j][0],a0h,a1h,a2h,a3h,bh4[0],bh4[1]);
                mmabf(acc[j][1],a0h,a1h,a2h,a3h,bh4[2],bh4[3]);
                mmabf(acc[j][0],a0l,a1l,a2l,a3l,bh4[0],bh4[1]);
                mmabf(acc[j][1],a0l,a1l,a2l,a3l,bh4[2],bh4[3]);
                mmabf(acc[j][0],a0h,a1h,a2h,a3h,bl4[0],bl4[1]);
                mmabf(acc[j][1],a0h,a1h,a2h,a3h,bl4[2],bl4[3]);
            }
        }
        __syncthreads();
    }
    float* Of=(float*)smdyn;
    constexpr int NPASS=Z?1:2;
    for(int ps=0;ps<NPASS;ps++){
        if(Z || (w>>2)==ps){
            #pragma unroll
            for(int j=0;j<NJS;j++){
                int h=hf*16+r4, n=(jn0+j)*16+c2;
                Of[h*67+n]=acc[j][0][0];     Of[h*67+n+1]=acc[j][0][1];
                Of[(h+8)*67+n]=acc[j][0][2]; Of[(h+8)*67+n+1]=acc[j][0][3];
                Of[h*67+n+8]=acc[j][1][0];   Of[h*67+n+9]=acc[j][1][1];
                Of[(h+8)*67+n+8]=acc[j][1][2]; Of[(h+8)*67+n+9]=acc[j][1][3];
            }
        }
        __syncthreads();
        u16 *oh,*ol;
        if(Z){oh=g_Vh;ol=g_Vl;} else {oh=ps?g_Kh:g_Qh; ol=ps?g_Kl:g_Ql;}
        oh+=(size_t)b*NP*HC; ol+=(size_t)b*NP*HC;
        if(Z){
            for(int i=tid;i<4096;i+=256){
                int h=i>>6, n=i&63;
                u32 v=pack_hl(Of[h*67+n]);
                oh[(size_t)h*NP+n0+n]=(u16)v; ol[(size_t)h*NP+n0+n]=(u16)(v>>16);
            }
        } else {
            for(int i=tid;i<4096;i+=256){
                int n=i>>6, h=i&63;
                u32 v=pack_hl(Of[h*67+n]);
                oh[(size_t)(n0+n)*HC+h]=(u16)v; ol[(size_t)(n0+n)*HC+h]=(u16)(v>>16);
            }
        }
        __syncthreads();
    }
}

// fused launch: blockIdx.z selects Q/K (rgb) or V (hsi) body
__global__ __launch_bounds__(256,2) void proj_kernel(const float* __restrict__ rgb,
                                                     const float* __restrict__ hsi){
    if(blockIdx.z==0) proj_body<0>(rgb);
    else              proj_body<1>(hsi);
}

// ---------------- attn: 64q CTAs, jj-split warp pairs, cp.async -------------
#define TILEB 9216
#define BUFB  36864
__global__ __launch_bounds__(256,2) void attn_kernel(){
    unsigned char* sm=smdyn;
    const int tid=threadIdx.x, lane=tid&31, warp=tid>>5;
    const int n0=blockIdx.x*64, b=blockIdx.y;
    const size_t qb=(size_t)b*NP*HC, vb=(size_t)b*HC*NP;
    const u16 *Qhp=g_Qh+qb,*Qlp=g_Ql+qb,*Khp=g_Kh+qb,*Klp=g_Kl+qb;
    const u16 *Vhp=g_Vh+vb,*Vlp=g_Vl+vb;
    const u32 smb=s2u(sm);
    const int qsub=warp&3, jj0=(warp>>2)*2;
    const int q0=n0+qsub*16, r4=lane>>2, c2=(lane&3)*2;
    u32 qh[4][4], ql[4][4];
    #pragma unroll
    for(int ks=0;ks<4;ks++){
        size_t o00=(size_t)(q0+r4)*HC+ks*16+c2, o10=o00+8*HC, o01=o00+8, o11=o10+8;
        qh[ks][0]=*(const u32*)(Qhp+o00); qh[ks][1]=*(const u32*)(Qhp+o10);
        qh[ks][2]=*(const u32*)(Qhp+o01); qh[ks][3]=*(const u32*)(Qhp+o11);
        ql[ks][0]=*(const u32*)(Qlp+o00); ql[ks][1]=*(const u32*)(Qlp+o10);
        ql[ks][2]=*(const u32*)(Qlp+o01); ql[ks][3]=*(const u32*)(Qlp+o11);
    }
    const int mat=lane>>3, mr=((mat>>1)<<3)+(lane&7), hoff=(mat&1)<<3;
    float O[8][4];
    #pragma unroll
    for(int j=0;j<8;j++){O[j][0]=0;O[j][1]=0;O[j][2]=0;O[j][3]=0;}
    float rsA=0.f, rsB=0.f;
    auto stage=[&](int m0, int buf){
        u32 ba=smb+buf*BUFB;
        #pragma unroll
        for(int t=0;t<2;t++){
            int u=tid+t*256, r=u>>3, q=u&7;
            u32 so=(u32)(r*9+q)*16;
            cpa16(ba+so,         Khp+(size_t)(m0+r)*HC+q*8);
            cpa16(ba+TILEB+so,   Klp+(size_t)(m0+r)*HC+q*8);
            cpa16(ba+2*TILEB+so, Vhp+(size_t)r*NP+m0+q*8);
            cpa16(ba+3*TILEB+so, Vlp+(size_t)r*NP+m0+q*8);
        }
        asm volatile("cp.async.commit_group;":::"memory");
    };
    stage(0,0);
    asm volatile("cp.async.wait_group 0;":::"memory");
    __syncthreads();
    for(int it=0; it<25; it++){
        const int bsel=it&1;
        if(it<24) stage((it+1)*64, bsel^1);
        const u32 kb=smb+bsel*BUFB;
        #pragma unroll
        for(int jj=0;jj<2;jj++){
            const int j=jj0+jj;
            float c0[4]={0,0,0,0}, c1[4]={0,0,0,0};
            #pragma unroll
            for(int ks=0;ks<4;ks++){
                u32 kh4[4],kl4[4];
                u32 a=kb+(((j*16+mr)*72)+ks*16+hoff)*2;
                ldsm4(kh4,a); ldsm4(kl4,a+TILEB);
                mmabf(c0,qh[ks][0],qh[ks][1],qh[ks][2],qh[ks][3],kh4[0],kh4[1]);
                mmabf(c1,qh[ks][0],qh[ks][1],qh[ks][2],qh[ks][3],kh4[2],kh4[3]);
                mmabf(c0,ql[ks][0],ql[ks][1],ql[ks][2],ql[ks][3],kh4[0],kh4[1]);
                mmabf(c1,ql[ks][0],ql[ks][1],ql[ks][2],ql[ks][3],kh4[2],kh4[3]);
                mmabf(c0,qh[ks][0],qh[ks][1],qh[ks][2],qh[ks][3],kl4[0],kl4[1]);
                mmabf(c1,qh[ks][0],qh[ks][1],qh[ks][2],qh[ks][3],kl4[2],kl4[3]);
            }
            #pragma unroll
            for(int e=0;e<4;e++){ c0[e]=ex2f(c0[e]*L2E8); c1[e]=ex2f(c1[e]*L2E8); }
            rsA += (c0[0]+c0[1])+(c1[0]+c1[1]);
            rsB += (c0[2]+c0[3])+(c1[2]+c1[3]);
            u32 Ph4[4], Pl4[4];
            split2(c0[0],c0[1],Ph4[0],Pl4[0]);
            split2(c0[2],c0[3],Ph4[1],Pl4[1]);
            split2(c1[0],c1[1],Ph4[2],Pl4[2]);
            split2(c1[2],c1[3],Ph4[3],Pl4[3]);
            #pragma unroll
            for(int hh=0;hh<4;hh++){
                u32 vh4[4],vl4[4];
                u32 a=kb+2*TILEB+(((hh*16+mr)*72)+j*16+hoff)*2;
                ldsm4(vh4,a); ldsm4(vl4,a+TILEB);
                mmabf(O[hh*2],  Ph4[0],Ph4[1],Ph4[2],Ph4[3],vh4[0],vh4[1]);
                mmabf(O[hh*2+1],Ph4[0],Ph4[1],Ph4[2],Ph4[3],vh4[2],vh4[3]);
                mmabf(O[hh*2],  Pl4[0],Pl4[1],Pl4[2],Pl4[3],vh4[0],vh4[1]);
                mmabf(O[hh*2+1],Pl4[0],Pl4[1],Pl4[2],Pl4[3],vh4[2],vh4[3]);
                mmabf(O[hh*2],  Ph4[0],Ph4[1],Ph4[2],Ph4[3],vl4[0],vl4[1]);
                mmabf(O[hh*2+1],Ph4[0],Ph4[1],Ph4[2],Ph4[3],vl4[2],vl4[3]);
            }
        }
        asm volatile("cp.async.wait_group 0;":::"memory");
        __syncthreads();
    }
    rsA += __shfl_xor_sync(0xffffffffu,rsA,1); rsA += __shfl_xor_sync(0xffffffffu,rsA,2);
    rsB += __shfl_xor_sync(0xffffffffu,rsB,1); rsB += __shfl_xor_sync(0xffffffffu,rsB,2);
    float* Po=(float*)sm;
    float* Rs=(float*)(sm+16384);
    float* Of=(float*)(sm+17664);
    if(warp>=4){
        int base=(qsub*32+lane)*32;
        #pragma unroll
        for(int j=0;j<8;j++)
            #pragma unroll
            for(int e=0;e<4;e++) Po[base+j*4+e]=O[j][e];
        Rs[(qsub*32+lane)*2+0]=rsA;
        Rs[(qsub*32+lane)*2+1]=rsB;
    }
    __syncthreads();
    if(warp<4){
        int base=(qsub*32+lane)*32;
        #pragma unroll
        for(int j=0;j<8;j++)
            #pragma unroll
            for(int e=0;e<4;e++) O[j][e]+=Po[base+j*4+e];
        rsA+=Rs[(qsub*32+lane)*2+0];
        rsB+=Rs[(qsub*32+lane)*2+1];
        const float invA=1.f/rsA, invB=1.f/rsB;
        #pragma unroll
        for(int j=0;j<8;j++){
            int h=j*8+c2;
            Of[(qsub*16+r4)*68+h  ]=O[j][0]*invA;
            Of[(qsub*16+r4)*68+h+1]=O[j][1]*invA;
            Of[(qsub*16+r4+8)*68+h  ]=O[j][2]*invB;
            Of[(qsub*16+r4+8)*68+h+1]=O[j][3]*invB;
        }
    }
    __syncthreads();
    u16 *Rh=g_Rh+(size_t)b*HC*NP, *Rl=g_Rl+(size_t)b*HC*NP;
    for(int i=tid;i<4096;i+=256){
        int h=i>>6, n=i&63, gn=n0+n;
        u32 v=pack_hl(Of[n*68+h]);
        Rh[(size_t)h*NN+gn]=(u16)v; Rl[(size_t)h*NN+gn]=(u16)(v>>16);
    }
}

// ---------------- out: 64-n tiles, 3 CTAs/SM ---------------------------------
__global__ __launch_bounds__(256,3) void out_kernel(float* __restrict__ out){
    const int tid=threadIdx.x, lane=tid&31, w=tid>>5;
    const int n0=blockIdx.x*64, c0=blockIdx.y*128, b=blockIdx.z;
    const u32* sRh=(const u32*)(g_Rh+(size_t)b*HC*NP);
    const u32* sRl=(const u32*)(g_Rl+(size_t)b*HC*NP);
    u32* kh=(u32*)smdyn; u32* kl=(u32*)(smdyn+9216);
    #pragma unroll
    for(int t=0;t<8;t++){
        int i=tid+t*256, r=i>>5, ww=i&31;
        kh[r*36+ww]=sRh[(size_t)(n0+r)*32+ww];
        kl[r*36+ww]=sRl[(size_t)(n0+r)*32+ww];
    }
    __syncthreads();
    const u32 smb=s2u(smdyn);
    const int r4=lane>>2, c2=(lane&3)*2;
    const int mat=lane>>3, mr=((mat>>1)<<3)+(lane&7), hoff=(mat&1)<<3;
    float acc[4][2][4];
    #pragma unroll
    for(int j=0;j<4;j++)
        #pragma unroll
        for(int g=0;g<2;g++){acc[j][g][0]=0;acc[j][g][1]=0;acc[j][g][2]=0;acc[j][g][3]=0;}
    #pragma unroll
    for(int ks=0;ks<4;ks++){
        size_t o=(size_t)(c0+w*16+r4)*HC + ks*16+c2;
        u32 a0h=*(const u32*)(g_Woh+o),   a1h=*(const u32*)(g_Woh+o+8*HC);
        u32 a2h=*(const u32*)(g_Woh+o+8), a3h=*(const u32*)(g_Woh+o+8*HC+8);
        u32 a0l=*(const u32*)(g_Wol+o),   a1l=*(const u32*)(g_Wol+o+8*HC);
        u32 a2l=*(const u32*)(g_Wol+o+8), a3l=*(const u32*)(g_Wol+o+8*HC+8);
        #pragma unroll
        for(int j=0;j<4;j++){
            u32 bh4[4],bl4[4];
            u32 a=smb+((j*16+mr)*72+ks*16+hoff)*2;
            ldsm4(bh4,a); ldsm4(bl4,a+9216);
            mmabf(acc[j][0],a0h,a1h,a2h,a3h,bh4[0],bh4[1]);
            mmabf(acc[j][1],a0h,a1h,a2h,a3h,bh4[2],bh4[3]);
            mmabf(acc[j][0],a0l,a1l,a2l,a3l,bh4[0],bh4[1]);
            mmabf(acc[j][1],a0l,a1l,a2l,a3l,bh4[2],bh4[3]);
            mmabf(acc[j][0],a0h,a1h,a2h,a3h,bl4[0],bl4[1]);
            mmabf(acc[j][1],a0h,a1h,a2h,a3h,bl4[2],bl4[3]);
        }
    }
    float* ob=out+(size_t)b*CC*NN;
    const int cc=c0+w*16+r4;
    #pragma unroll
    for(int j=0;j<4;j++){
        int nn=n0+j*16+c2;
        *(float2*)&ob[(size_t)cc*NN+nn]      =make_float2(acc[j][0][0],acc[j][0][1]);
        *(float2*)&ob[(size_t)(cc+8)*NN+nn]  =make_float2(acc[j][0][2],acc[j][0][3]);
        *(float2*)&ob[(size_t)cc*NN+nn+8]    =make_float2(acc[j][1][0],acc[j][1][1]);
        *(float2*)&ob[(size_t)(cc+8)*NN+nn+8]=make_float2(acc[j][1][2],acc[j][1][3]);
    }
}

extern "C" void kernel_launch(void* const* d_in, const int* in_sizes, int n_in,
                              void* d_out, int out_size){
    const float* rgb=(const float*)d_in[0];
    const float* hsi=(const float*)d_in[1];
    const float* wq =(const float*)d_in[2];
    const float* wk =(const float*)d_in[3];
    const float* wv =(const float*)d_in[4];
    const float* wo =(const float*)d_in[5];
    float* out=(float*)d_out;

    cudaFuncSetAttribute(proj_kernel, cudaFuncAttributeMaxDynamicSharedMemorySize, 2*PBUF);
    cudaFuncSetAttribute(attn_kernel, cudaFuncAttributeMaxDynamicSharedMemorySize, 2*BUFB);
    prep_kernel<<<512,256>>>(wq,wk,wv,wo);
    proj_kernel<<<dim3(25,BB,2),256,2*PBUF>>>(rgb,hsi);
    attn_kernel<<<dim3(25,BB),256,2*BUFB>>>();
    out_kernel<<<dim3(25,4,BB),256,18432>>>(out);
}